// round 2
// baseline (speedup 1.0000x reference)
#include <cuda_runtime.h>

#define KD 512
#define DD 1024
#define KK (KD*KD)
#define U2 (2*KK)
#define LMB 1000.0f
#define NS_ITERS 10
#define CG_ITERS 20

// Scratch: G,H,H2,T,mask,B,R,P,W each [2K x K] + scalar vectors
__device__ float g_scratch[9ull*U2 + 4096];

// mode enum for gemm_nn epilogue
#define M_PLAIN    0
#define M_TWOMINUS 1
#define M_MASKDOT  2
#define M_DOT      3
#define M_COPYDOT  4

// ---------------------------------------------------------------------------
// s = max(max(ea), max(eb)); zero fro2
__global__ void k_prep(const float* __restrict__ ea, const float* __restrict__ eb,
                       float* __restrict__ sp, float* __restrict__ fro2) {
    __shared__ float sm[512];
    int t = threadIdx.x;
    sm[t] = fmaxf(ea[t], eb[t]);
    __syncthreads();
    for (int s = 256; s; s >>= 1) {
        if (t < s) sm[t] = fmaxf(sm[t], sm[t + s]);
        __syncthreads();
    }
    if (t == 0) { sp[0] = sm[0]; fro2[0] = 0.f; fro2[1] = 0.f; }
}

// mask_ab[i,j] and mask_ba = mask_ab^T, stacked [2K x K]
__global__ void k_mask(const float* __restrict__ ea, const float* __restrict__ eb,
                       const float* __restrict__ sp, float* __restrict__ maskS) {
    int j = blockIdx.x * 16 + threadIdx.x;  // Ka index
    int i = blockIdx.y * 16 + threadIdx.y;  // Kb index
    float s = sp[0];
    float ga = ea[j] / s, gb = eb[i] / s;
    float ga2 = ga * ga + 1.f, gb2 = gb * gb + 1.f;
    float mre = gb / gb2 - ga / ga2;
    float mim = 1.f / gb2 - 1.f / ga2;
    float m = mre * mre + mim * mim;
    maskS[i * KD + j] = m;              // mask_ab
    maskS[KK + j * KD + i] = m;         // mask_ba (= transpose)
}

// ---------------------------------------------------------------------------
// Gram GEMMs (TN): z=0: G_a=A^T A ; z=1: G_b=B^T B ; z=2: Bvec_top = B^T A
__global__ __launch_bounds__(256, 2)
void gemm_tn(const float* __restrict__ A, const float* __restrict__ Bm,
             float* __restrict__ G, float* __restrict__ Bv) {
    int z = blockIdx.z;
    const float* M1 = (z == 0) ? A : Bm;
    const float* M2 = (z == 1) ? Bm : A;
    float* O = (z == 0) ? G : ((z == 1) ? (G + KK) : Bv);

    __shared__ float As[16][64];
    __shared__ float Bs[16][64];
    int row0 = blockIdx.y * 64, col0 = blockIdx.x * 64;
    int t = threadIdx.x, tx = t & 15, ty = t >> 4;
    float acc[4][4] = {};

    for (int k0 = 0; k0 < DD; k0 += 16) {
#pragma unroll
        for (int i = 0; i < 4; i++) {
            int idx = t + i * 256;
            int m = idx & 63, kk = idx >> 6;
            As[kk][m] = M1[(k0 + kk) * KD + row0 + m];
            Bs[kk][m] = M2[(k0 + kk) * KD + col0 + m];
        }
        __syncthreads();
#pragma unroll
        for (int kk = 0; kk < 16; kk++) {
            float4 a = *(const float4*)&As[kk][ty * 4];
            float4 b = *(const float4*)&Bs[kk][tx * 4];
            acc[0][0] += a.x * b.x; acc[0][1] += a.x * b.y; acc[0][2] += a.x * b.z; acc[0][3] += a.x * b.w;
            acc[1][0] += a.y * b.x; acc[1][1] += a.y * b.y; acc[1][2] += a.y * b.z; acc[1][3] += a.y * b.w;
            acc[2][0] += a.z * b.x; acc[2][1] += a.z * b.y; acc[2][2] += a.z * b.z; acc[2][3] += a.z * b.w;
            acc[3][0] += a.w * b.x; acc[3][1] += a.w * b.y; acc[3][2] += a.w * b.z; acc[3][3] += a.w * b.w;
        }
        __syncthreads();
    }
    int r = row0 + ty * 4, c = col0 + tx * 4;
#pragma unroll
    for (int i = 0; i < 4; i++) {
        float4 o = make_float4(acc[i][0], acc[i][1], acc[i][2], acc[i][3]);
        *(float4*)&O[(r + i) * KD + c] = o;
    }
}

// ---------------------------------------------------------------------------
// NN GEMM: Out[r,:] = L[r,:] @ R_d  (r in [0,2K); d = r>=K ? b : a), with fused
// epilogues for Newton-Schulz and PCG.
__global__ __launch_bounds__(256, 2)
void gemm_nn(const float* __restrict__ L, const float* __restrict__ Ra,
             const float* __restrict__ Rb, float* __restrict__ Out,
             int mode, const float* __restrict__ maskS, float* __restrict__ dotv,
             float* __restrict__ copyOut, const float* __restrict__ prevE) {
    __shared__ float Ls[64][17];
    __shared__ float Bs[16][64];
    int row0 = blockIdx.y * 64, col0 = blockIdx.x * 64;
    const float* R = (row0 < KD) ? Ra : Rb;
    int t = threadIdx.x, tx = t & 15, ty = t >> 4;
    float acc[4][4] = {};

    for (int k0 = 0; k0 < KD; k0 += 16) {
#pragma unroll
        for (int i = 0; i < 4; i++) {
            int idx = t + i * 256;
            int m = idx >> 4, kk = idx & 15;
            Ls[m][kk] = L[(row0 + m) * KD + k0 + kk];
        }
#pragma unroll
        for (int i = 0; i < 4; i++) {
            int idx = t + i * 256;
            int kk = idx >> 6, c = idx & 63;
            Bs[kk][c] = R[(k0 + kk) * KD + col0 + c];
        }
        __syncthreads();
#pragma unroll
        for (int kk = 0; kk < 16; kk++) {
            float a0 = Ls[ty * 4 + 0][kk];
            float a1 = Ls[ty * 4 + 1][kk];
            float a2 = Ls[ty * 4 + 2][kk];
            float a3 = Ls[ty * 4 + 3][kk];
            float4 b = *(const float4*)&Bs[kk][tx * 4];
            acc[0][0] += a0 * b.x; acc[0][1] += a0 * b.y; acc[0][2] += a0 * b.z; acc[0][3] += a0 * b.w;
            acc[1][0] += a1 * b.x; acc[1][1] += a1 * b.y; acc[1][2] += a1 * b.z; acc[1][3] += a1 * b.w;
            acc[2][0] += a2 * b.x; acc[2][1] += a2 * b.y; acc[2][2] += a2 * b.z; acc[2][3] += a2 * b.w;
            acc[3][0] += a3 * b.x; acc[3][1] += a3 * b.y; acc[3][2] += a3 * b.z; acc[3][3] += a3 * b.w;
        }
        __syncthreads();
    }

    int r = row0 + ty * 4, c = col0 + tx * 4;
    float dpart[4] = {0.f, 0.f, 0.f, 0.f};
#pragma unroll
    for (int i = 0; i < 4; i++) {
        float4 o = make_float4(acc[i][0], acc[i][1], acc[i][2], acc[i][3]);
        int off = (r + i) * KD + c;
        if (mode == M_TWOMINUS) {
            float4 p = *(const float4*)&prevE[off];
            o.x = 2.f * p.x - o.x;
            o.y = 2.f * p.y - o.y;
            o.z = 2.f * p.z - o.z;
            o.w = 2.f * p.w - o.w;
        } else if (mode == M_MASKDOT) {
            float4 mk = *(const float4*)&maskS[off];
            float4 lv = *(const float4*)&L[off];
            o.x += LMB * mk.x * lv.x;
            o.y += LMB * mk.y * lv.y;
            o.z += LMB * mk.z * lv.z;
            o.w += LMB * mk.w * lv.w;
            dpart[i] = lv.x * o.x + lv.y * o.y + lv.z * o.z + lv.w * o.w;
        } else if (mode == M_DOT || mode == M_COPYDOT) {
            float4 lv = *(const float4*)&L[off];
            dpart[i] = lv.x * o.x + lv.y * o.y + lv.z * o.z + lv.w * o.w;
            if (mode == M_COPYDOT) *(float4*)&copyOut[off] = o;
        }
        *(float4*)&Out[off] = o;
    }
    if (mode >= M_MASKDOT) {
#pragma unroll
        for (int i = 0; i < 4; i++) {
            float v = dpart[i];
            v += __shfl_xor_sync(0xffffffffu, v, 8, 16);
            v += __shfl_xor_sync(0xffffffffu, v, 4, 16);
            v += __shfl_xor_sync(0xffffffffu, v, 2, 16);
            v += __shfl_xor_sync(0xffffffffu, v, 1, 16);
            if (tx == 0) atomicAdd(&dotv[r + i], v);
        }
    }
}

// ---------------------------------------------------------------------------
// Transpose Bvec top half into bottom half: Bv[K+j][i] = Bv[i][j]
__global__ void k_transB(float* __restrict__ Bv) {
    __shared__ float tile[32][33];
    int bx = blockIdx.x * 32, by = blockIdx.y * 32;
    int tx = threadIdx.x, ty = threadIdx.y;  // (32, 8)
#pragma unroll
    for (int i = 0; i < 32; i += 8)
        tile[ty + i][tx] = Bv[(by + ty + i) * KD + bx + tx];
    __syncthreads();
#pragma unroll
    for (int i = 0; i < 32; i += 8)
        Bv[(KD + bx + ty + i) * KD + by + tx] = tile[tx][ty + i];
}

// Frobenius^2 of G_a (d=0) / G_b (d=1)
__global__ void k_frob(const float* __restrict__ G, float* __restrict__ fro2) {
    int d = blockIdx.y;
    int idx = d * KK + (blockIdx.x * 256 + threadIdx.x) * 4;
    float4 g = *(const float4*)&G[idx];
    float v = g.x * g.x + g.y * g.y + g.z * g.z + g.w * g.w;
#pragma unroll
    for (int o = 16; o; o >>= 1) v += __shfl_xor_sync(0xffffffffu, v, o);
    __shared__ float sm[8];
    if ((threadIdx.x & 31) == 0) sm[threadIdx.x >> 5] = v;
    __syncthreads();
    if (threadIdx.x < 8) {
        v = sm[threadIdx.x];
#pragma unroll
        for (int o = 4; o; o >>= 1) v += __shfl_xor_sync(0xffu, v, o, 8);
        if (threadIdx.x == 0) atomicAdd(&fro2[d], v);
    }
}

// H0 = 2cI - c^2 G  (one analytic Newton-Schulz step from cI), c = 1/||G||_F
__global__ void k_initH(const float* __restrict__ G, const float* __restrict__ fro2,
                        float* __restrict__ H) {
    int idx = blockIdx.x * 256 + threadIdx.x;  // [0, U2)
    int r = idx >> 9, c = idx & (KD - 1);
    int d = r >> 9, rr = r & (KD - 1);
    float cc = rsqrtf(fro2[d]);
    H[idx] = (rr == c ? 2.f * cc : 0.f) - cc * cc * G[idx];
}

// X = 0, R = B, zero scalar vectors
__global__ void k_init_state(const float* __restrict__ Bv, float* __restrict__ X,
                             float* __restrict__ Rr, float* __restrict__ rho,
                             float* __restrict__ pq, float* __restrict__ rhon) {
    int idx = blockIdx.x * 256 + threadIdx.x;
    X[idx] = 0.f;
    Rr[idx] = Bv[idx];
    if (idx < 2 * KD) { rho[idx] = 0.f; pq[idx] = 0.f; rhon[idx] = 0.f; }
}

// alpha = rho/pq; X += a P; R -= a W; zero rhon
__global__ void k_update1(float* __restrict__ X, float* __restrict__ Rr,
                          const float* __restrict__ P, const float* __restrict__ W,
                          const float* __restrict__ rho, const float* __restrict__ pq,
                          float* __restrict__ rhon) {
    int r = blockIdx.x, t = threadIdx.x;
    float al = rho[r] / (pq[r] + 1e-30f);
    int off = r * KD + t * 4;
    float4 p = *(const float4*)&P[off];
    float4 w = *(const float4*)&W[off];
    float4 x = *(float4*)&X[off];
    float4 rr = *(float4*)&Rr[off];
    x.x += al * p.x; x.y += al * p.y; x.z += al * p.z; x.w += al * p.w;
    rr.x -= al * w.x; rr.y -= al * w.y; rr.z -= al * w.z; rr.w -= al * w.w;
    *(float4*)&X[off] = x;
    *(float4*)&Rr[off] = rr;
    if (t == 0) rhon[r] = 0.f;
}

// beta = rhon/rho; P = W + b P; rho = rhon; zero pq
__global__ void k_update2(float* __restrict__ P, const float* __restrict__ W,
                          float* __restrict__ rho, const float* __restrict__ rhon,
                          float* __restrict__ pq) {
    int r = blockIdx.x, t = threadIdx.x;
    float be = rhon[r] / (rho[r] + 1e-30f);
    int off = r * KD + t * 4;
    float4 p = *(const float4*)&P[off];
    float4 w = *(const float4*)&W[off];
    p.x = w.x + be * p.x; p.y = w.y + be * p.y;
    p.z = w.z + be * p.z; p.w = w.w + be * p.w;
    *(float4*)&P[off] = p;
    if (t == 0) { rho[r] = rhon[r]; pq[r] = 0.f; }
}

// ---------------------------------------------------------------------------
extern "C" void kernel_launch(void* const* d_in, const int* in_sizes, int n_in,
                              void* d_out, int out_size) {
    (void)in_sizes; (void)n_in; (void)out_size;
    const float* A  = (const float*)d_in[0];  // [D, Ka]
    const float* Bm = (const float*)d_in[1];  // [D, Kb]
    const float* ea = (const float*)d_in[2];  // [Ka]
    const float* eb = (const float*)d_in[3];  // [Kb]
    float* X = (float*)d_out;                 // [2K, K]: fmap_12 then fmap_21

    float* S = nullptr;
    cudaGetSymbolAddress((void**)&S, g_scratch);
    float* G    = S;
    float* H    = S + 1ull * U2;
    float* H2   = S + 2ull * U2;
    float* T    = S + 3ull * U2;
    float* mask = S + 4ull * U2;
    float* Bv   = S + 5ull * U2;
    float* Rr   = S + 6ull * U2;
    float* P    = S + 7ull * U2;
    float* W    = S + 8ull * U2;
    float* rho  = S + 9ull * U2;
    float* pq   = rho + 1024;
    float* rhon = pq + 1024;
    float* fro2 = rhon + 1024;
    float* sp   = fro2 + 2;

    dim3 gN(KD / 64, (2 * KD) / 64);  // (8, 16)

    k_prep<<<1, 512>>>(ea, eb, sp, fro2);
    k_mask<<<dim3(KD / 16, KD / 16), dim3(16, 16)>>>(ea, eb, sp, mask);
    gemm_tn<<<dim3(8, 8, 3), 256>>>(A, Bm, G, Bv);
    k_transB<<<dim3(16, 16), dim3(32, 8)>>>(Bv);
    k_frob<<<dim3(256, 2), 256>>>(G, fro2);
    k_initH<<<U2 / 256, 256>>>(G, fro2, H);

    // Newton-Schulz: H <- H(2I - G H), ping-pong H/H2
    float* hc = H;
    float* ha = H2;
    for (int i = 0; i < NS_ITERS; i++) {
        gemm_nn<<<gN, 256>>>(G, hc, hc + KK, T, M_PLAIN, nullptr, nullptr, nullptr, nullptr);
        gemm_nn<<<gN, 256>>>(hc, T, T + KK, ha, M_TWOMINUS, nullptr, nullptr, nullptr, hc);
        float* tmp = hc; hc = ha; ha = tmp;
    }

    // PCG init: X=0, R=b, Z=H r, P=Z, rho = r.z
    k_init_state<<<U2 / 256, 256>>>(Bv, X, Rr, rho, pq, rhon);
    gemm_nn<<<gN, 256>>>(Rr, hc, hc + KK, W, M_COPYDOT, nullptr, rho, P, nullptr);

    for (int i = 0; i < CG_ITERS; i++) {
        // W = A p = P@G_d + lambda*mask.*P ; pq += p.q
        gemm_nn<<<gN, 256>>>(P, G, G + KK, W, M_MASKDOT, mask, pq, nullptr, nullptr);
        k_update1<<<1024, 128>>>(X, Rr, P, W, rho, pq, rhon);
        // W = H r ; rhon += r.z
        gemm_nn<<<gN, 256>>>(Rr, hc, hc + KK, W, M_DOT, nullptr, rhon, nullptr, nullptr);
        k_update2<<<1024, 128>>>(P, W, rho, rhon, pq);
    }
}

// round 6
// speedup vs baseline: 2.0348x; 2.0348x over previous
#include <cuda_runtime.h>

#define KD 512
#define DD 1024
#define KK (KD*KD)
#define U2 (2*KK)
#define LMB 1000.0f
#define CG_ITERS 40

// Scratch: G(U2), mask(U2), Bv(U2), R(U2), P(U2), W partials(4*U2) + scalars
__device__ float g_scratch[9ull*U2 + 4096];

// ---------------------------------------------------------------------------
__global__ void k_prep(const float* __restrict__ ea, const float* __restrict__ eb,
                       float* __restrict__ sp) {
    __shared__ float sm[512];
    int t = threadIdx.x;
    sm[t] = fmaxf(ea[t], eb[t]);
    __syncthreads();
    for (int s = 256; s; s >>= 1) {
        if (t < s) sm[t] = fmaxf(sm[t], sm[t + s]);
        __syncthreads();
    }
    if (t == 0) sp[0] = sm[0];
}

// mask_ab[i,j] and mask_ba = mask_ab^T, stacked [2K x K]
__global__ void k_mask(const float* __restrict__ ea, const float* __restrict__ eb,
                       const float* __restrict__ sp, float* __restrict__ maskS) {
    int j = blockIdx.x * 16 + threadIdx.x;  // Ka index
    int i = blockIdx.y * 16 + threadIdx.y;  // Kb index
    float s = sp[0];
    float ga = ea[j] / s, gb = eb[i] / s;
    float ga2 = ga * ga + 1.f, gb2 = gb * gb + 1.f;
    float mre = gb / gb2 - ga / ga2;
    float mim = 1.f / gb2 - 1.f / ga2;
    float m = mre * mre + mim * mim;
    maskS[i * KD + j] = m;              // mask_ab
    maskS[KK + j * KD + i] = m;         // mask_ba (= transpose)
}

// ---------------------------------------------------------------------------
// Gram GEMMs (TN): z=0: G_a=A^T A ; z=1: G_b=B^T B ; z=2: Bvec_top = B^T A
__global__ __launch_bounds__(256, 2)
void gemm_tn(const float* __restrict__ A, const float* __restrict__ Bm,
             float* __restrict__ G, float* __restrict__ Bv) {
    int z = blockIdx.z;
    const float* M1 = (z == 0) ? A : Bm;
    const float* M2 = (z == 1) ? Bm : A;
    float* O = (z == 0) ? G : ((z == 1) ? (G + KK) : Bv);

    __shared__ float As[16][64];
    __shared__ float Bs[16][64];
    int row0 = blockIdx.y * 64, col0 = blockIdx.x * 64;
    int t = threadIdx.x, tx = t & 15, ty = t >> 4;
    float acc[4][4] = {};

    for (int k0 = 0; k0 < DD; k0 += 16) {
#pragma unroll
        for (int i = 0; i < 4; i++) {
            int idx = t + i * 256;
            int m = idx & 63, kk = idx >> 6;
            As[kk][m] = M1[(k0 + kk) * KD + row0 + m];
            Bs[kk][m] = M2[(k0 + kk) * KD + col0 + m];
        }
        __syncthreads();
#pragma unroll
        for (int kk = 0; kk < 16; kk++) {
            float4 a = *(const float4*)&As[kk][ty * 4];
            float4 b = *(const float4*)&Bs[kk][tx * 4];
            acc[0][0] += a.x * b.x; acc[0][1] += a.x * b.y; acc[0][2] += a.x * b.z; acc[0][3] += a.x * b.w;
            acc[1][0] += a.y * b.x; acc[1][1] += a.y * b.y; acc[1][2] += a.y * b.z; acc[1][3] += a.y * b.w;
            acc[2][0] += a.z * b.x; acc[2][1] += a.z * b.y; acc[2][2] += a.z * b.z; acc[2][3] += a.z * b.w;
            acc[3][0] += a.w * b.x; acc[3][1] += a.w * b.y; acc[3][2] += a.w * b.z; acc[3][3] += a.w * b.w;
        }
        __syncthreads();
    }
    int r = row0 + ty * 4, c = col0 + tx * 4;
#pragma unroll
    for (int i = 0; i < 4; i++) {
        float4 o = make_float4(acc[i][0], acc[i][1], acc[i][2], acc[i][3]);
        *(float4*)&O[(r + i) * KD + c] = o;
    }
}

// ---------------------------------------------------------------------------
// Transpose Bvec top half into bottom half: Bv[K+j][i] = Bv[i][j]
__global__ void k_transB(float* __restrict__ Bv) {
    __shared__ float tile[32][33];
    int bx = blockIdx.x * 32, by = blockIdx.y * 32;
    int tx = threadIdx.x, ty = threadIdx.y;  // (32, 8)
#pragma unroll
    for (int i = 0; i < 32; i += 8)
        tile[ty + i][tx] = Bv[(by + ty + i) * KD + bx + tx];
    __syncthreads();
#pragma unroll
    for (int i = 0; i < 32; i += 8)
        Bv[(KD + bx + ty + i) * KD + by + tx] = tile[tx][ty + i];
}

// diag of G_a / G_b
__global__ void k_diag(const float* __restrict__ G, float* __restrict__ dg) {
    int idx = blockIdx.x * 256 + threadIdx.x;  // [0, 1024)
    int d = idx >> 9, j = idx & (KD - 1);
    dg[idx] = G[d * KK + j * KD + j];
}

// ---------------------------------------------------------------------------
// Split-K NN GEMM: Wp[z] partial = L[tile] @ R_d[kchunk]  (plain, no epilogue)
// 128x128 tile, 256 threads, 8x8/thread, BK=8 double-buffered, splitK=4.
__global__ __launch_bounds__(256, 1)
void gemm_nn_sk(const float* __restrict__ L, const float* __restrict__ Ga,
                const float* __restrict__ Gb, float* __restrict__ Wp) {
    __shared__ float Ls[2][8][128];
    __shared__ float Rs[2][8][128];
    int r0 = blockIdx.y * 128, c0 = blockIdx.x * 128;
    int kbase = blockIdx.z * 128;
    const float* Rm = (r0 < KD) ? Ga : Gb;
    float* Out = Wp + (size_t)blockIdx.z * U2;

    int t = threadIdx.x;
    int tx = t & 15, ty = t >> 4;
    int lm = t >> 1, lk4 = (t & 1) * 4;   // L loader: row lm, k-offset lk4
    int rk = t >> 5, rc4 = (t & 31) * 4;  // R loader: k-row rk, col rc4

    float acc[8][8] = {};

    // prologue: stage 0
    float4 lv = *(const float4*)&L[(size_t)(r0 + lm) * KD + kbase + lk4];
    float4 rv = *(const float4*)&Rm[(size_t)(kbase + rk) * KD + c0 + rc4];
    Ls[0][lk4 + 0][lm] = lv.x; Ls[0][lk4 + 1][lm] = lv.y;
    Ls[0][lk4 + 2][lm] = lv.z; Ls[0][lk4 + 3][lm] = lv.w;
    *(float4*)&Rs[0][rk][rc4] = rv;
    __syncthreads();

    int buf = 0;
#pragma unroll 1
    for (int ks = 0; ks < 16; ks++) {
        if (ks + 1 < 16) {
            int k0 = kbase + (ks + 1) * 8;
            lv = *(const float4*)&L[(size_t)(r0 + lm) * KD + k0 + lk4];
            rv = *(const float4*)&Rm[(size_t)(k0 + rk) * KD + c0 + rc4];
        }
#pragma unroll
        for (int kk = 0; kk < 8; kk++) {
            float a[8], b[8];
            *(float4*)&a[0] = *(const float4*)&Ls[buf][kk][ty * 8];
            *(float4*)&a[4] = *(const float4*)&Ls[buf][kk][ty * 8 + 4];
            *(float4*)&b[0] = *(const float4*)&Rs[buf][kk][tx * 8];
            *(float4*)&b[4] = *(const float4*)&Rs[buf][kk][tx * 8 + 4];
#pragma unroll
            for (int i = 0; i < 8; i++)
#pragma unroll
                for (int j = 0; j < 8; j++) acc[i][j] += a[i] * b[j];
        }
        if (ks + 1 < 16) {
            int nb = buf ^ 1;
            Ls[nb][lk4 + 0][lm] = lv.x; Ls[nb][lk4 + 1][lm] = lv.y;
            Ls[nb][lk4 + 2][lm] = lv.z; Ls[nb][lk4 + 3][lm] = lv.w;
            *(float4*)&Rs[nb][rk][rc4] = rv;
            __syncthreads();
            buf = nb;
        }
    }

#pragma unroll
    for (int i = 0; i < 8; i++) {
        size_t off = (size_t)(r0 + ty * 8 + i) * KD + c0 + tx * 8;
        *(float4*)&Out[off]     = make_float4(acc[i][0], acc[i][1], acc[i][2], acc[i][3]);
        *(float4*)&Out[off + 4] = make_float4(acc[i][4], acc[i][5], acc[i][6], acc[i][7]);
    }
}

// ---------------------------------------------------------------------------
// Jacobi-PCG fused vector kernels: one block (128 thr) per row (512 elems).

__device__ __forceinline__ float rowReduce(float v, float* sm, int t) {
#pragma unroll
    for (int o = 16; o; o >>= 1) v += __shfl_xor_sync(0xffffffffu, v, o);
    if ((t & 31) == 0) sm[t >> 5] = v;
    __syncthreads();
    return sm[0] + sm[1] + sm[2] + sm[3];
}

// x=0, r=b, z=r/d, p=z, rho=r.z
__global__ void k_cg_init(const float* __restrict__ Bv, float* __restrict__ X,
                          float* __restrict__ R, float* __restrict__ P,
                          const float* __restrict__ mask, const float* __restrict__ dg,
                          float* __restrict__ rho) {
    __shared__ float s1[4];
    int r = blockIdx.x, t = threadIdx.x;
    int off = r * KD + t * 4;
    float4 b = *(const float4*)&Bv[off];
    float4 m = *(const float4*)&mask[off];
    float4 dv = *(const float4*)&dg[((r >> 9) << 9) + t * 4];
    float4 z;
    z.x = b.x / (dv.x + LMB * m.x);
    z.y = b.y / (dv.y + LMB * m.y);
    z.z = b.z / (dv.z + LMB * m.z);
    z.w = b.w / (dv.w + LMB * m.w);
    float rz = b.x * z.x + b.y * z.y + b.z * z.z + b.w * z.w;
    rz = rowReduce(rz, s1, t);
    *(float4*)&X[off] = make_float4(0.f, 0.f, 0.f, 0.f);
    *(float4*)&R[off] = b;
    *(float4*)&P[off] = z;
    if (t == 0) rho[r] = rz;
}

// w = sum(W partials) + lmbda*m.*p; alpha=rho/(p.w); x+=a p; r-=a w;
// z=r/d; rhon=r.z; beta=rhon/rho; p=z+beta p; rho=rhon
__global__ void k_cg_step(float* __restrict__ X, float* __restrict__ R,
                          float* __restrict__ P, const float* __restrict__ Wp,
                          const float* __restrict__ mask, const float* __restrict__ dg,
                          float* __restrict__ rho) {
    __shared__ float s1[4], s2[4];
    int r = blockIdx.x, t = threadIdx.x;
    int off = r * KD + t * 4;
    float4 p  = *(const float4*)&P[off];
    float4 w  = *(const float4*)&Wp[off];
    float4 w1 = *(const float4*)&Wp[(size_t)U2 + off];
    float4 w2 = *(const float4*)&Wp[(size_t)2 * U2 + off];
    float4 w3 = *(const float4*)&Wp[(size_t)3 * U2 + off];
    float4 m  = *(const float4*)&mask[off];
    float4 dv = *(const float4*)&dg[((r >> 9) << 9) + t * 4];
    w.x += w1.x + w2.x + w3.x + LMB * m.x * p.x;
    w.y += w1.y + w2.y + w3.y + LMB * m.y * p.y;
    w.z += w1.z + w2.z + w3.z + LMB * m.z * p.z;
    w.w += w1.w + w2.w + w3.w + LMB * m.w * p.w;

    float pq = p.x * w.x + p.y * w.y + p.z * w.z + p.w * w.w;
    pq = rowReduce(pq, s1, t);
    float rho_old = rho[r];
    float al = rho_old / (pq + 1e-30f);

    float4 x = *(float4*)&X[off];
    float4 rv = *(float4*)&R[off];
    x.x += al * p.x; x.y += al * p.y; x.z += al * p.z; x.w += al * p.w;
    rv.x -= al * w.x; rv.y -= al * w.y; rv.z -= al * w.z; rv.w -= al * w.w;

    float4 z;
    z.x = rv.x / (dv.x + LMB * m.x);
    z.y = rv.y / (dv.y + LMB * m.y);
    z.z = rv.z / (dv.z + LMB * m.z);
    z.w = rv.w / (dv.w + LMB * m.w);
    float rz = rv.x * z.x + rv.y * z.y + rv.z * z.z + rv.w * z.w;
    __syncthreads();  // protect s1 reuse ordering before s2 writes
    rz = rowReduce(rz, s2, t);
    float be = rz / (rho_old > 0.f ? rho_old + 1e-30f : (rho_old - 1e-30f));

    p.x = z.x + be * p.x; p.y = z.y + be * p.y;
    p.z = z.z + be * p.z; p.w = z.w + be * p.w;

    *(float4*)&X[off] = x;
    *(float4*)&R[off] = rv;
    *(float4*)&P[off] = p;
    if (t == 0) rho[r] = rz;
}

// ---------------------------------------------------------------------------
extern "C" void kernel_launch(void* const* d_in, const int* in_sizes, int n_in,
                              void* d_out, int out_size) {
    (void)in_sizes; (void)n_in; (void)out_size;
    const float* A  = (const float*)d_in[0];  // [D, Ka]
    const float* Bm = (const float*)d_in[1];  // [D, Kb]
    const float* ea = (const float*)d_in[2];  // [Ka]
    const float* eb = (const float*)d_in[3];  // [Kb]
    float* X = (float*)d_out;                 // [2K, K]: fmap_12 then fmap_21

    float* S = nullptr;
    cudaGetSymbolAddress((void**)&S, g_scratch);
    float* G    = S;                 // [2][K][K]
    float* mask = S + 1ull * U2;
    float* Bv   = S + 2ull * U2;
    float* R    = S + 3ull * U2;
    float* P    = S + 4ull * U2;
    float* W    = S + 5ull * U2;     // 4 partial buffers
    float* dg   = S + 9ull * U2;     // 1024
    float* rho  = dg + 1024;         // 1024
    float* sp   = rho + 1024;

    k_prep<<<1, 512>>>(ea, eb, sp);
    k_mask<<<dim3(KD / 16, KD / 16), dim3(16, 16)>>>(ea, eb, sp, mask);
    gemm_tn<<<dim3(8, 8, 3), 256>>>(A, Bm, G, Bv);
    k_transB<<<dim3(16, 16), dim3(32, 8)>>>(Bv);
    k_diag<<<4, 256>>>(G, dg);
    k_cg_init<<<1024, 128>>>(Bv, X, R, P, mask, dg, rho);

    for (int i = 0; i < CG_ITERS; i++) {
        gemm_nn_sk<<<dim3(4, 8, 4), 256>>>(P, G, G + KK, W);
        k_cg_step<<<1024, 128>>>(X, R, P, W, mask, dg, rho);
    }
}

// round 12
// speedup vs baseline: 2.2213x; 1.0917x over previous
#include <cuda_runtime.h>
#include <cuda_bf16.h>
#include <cstdint>

#define KD 512
#define DD 1024
#define KK (KD*KD)
#define U2 (2*KK)
#define LMB 1000.0f
#define ITERS_BF16 27
#define ITERS_F32  3

__device__ __align__(128) float g_scratch[12ull*U2 + 4096];

// ---------------------------------------------------------------------------
__device__ __forceinline__ uint32_t smem_u32(const void* p) {
    uint32_t a;
    asm("{ .reg .u64 t; cvta.to.shared.u64 t, %1; cvt.u32.u64 %0, t; }" : "=r"(a) : "l"(p));
    return a;
}
#define LDSM4(r0, r1, r2, r3, addr)                                         \
    asm volatile("ldmatrix.sync.aligned.m8n8.x4.shared.b16 {%0,%1,%2,%3}, [%4];" \
                 : "=r"(r0), "=r"(r1), "=r"(r2), "=r"(r3) : "r"(addr))

__device__ __forceinline__ void mma16816(float* c, uint32_t a0, uint32_t a1,
                                         uint32_t a2, uint32_t a3,
                                         uint32_t b0, uint32_t b1) {
    asm volatile("mma.sync.aligned.m16n8k16.row.col.f32.bf16.bf16.f32 "
                 "{%0,%1,%2,%3},{%4,%5,%6,%7},{%8,%9},{%0,%1,%2,%3};"
                 : "+f"(c[0]), "+f"(c[1]), "+f"(c[2]), "+f"(c[3])
                 : "r"(a0), "r"(a1), "r"(a2), "r"(a3), "r"(b0), "r"(b1));
}

// ---------------------------------------------------------------------------
__global__ void k_prep(const float* __restrict__ ea, const float* __restrict__ eb,
                       float* __restrict__ sp) {
    __shared__ float sm[512];
    int t = threadIdx.x;
    sm[t] = fmaxf(ea[t], eb[t]);
    __syncthreads();
    for (int s = 256; s; s >>= 1) {
        if (t < s) sm[t] = fmaxf(sm[t], sm[t + s]);
        __syncthreads();
    }
    if (t == 0) sp[0] = sm[0];
}

__global__ void k_mask(const float* __restrict__ ea, const float* __restrict__ eb,
                       const float* __restrict__ sp, float* __restrict__ maskS) {
    int j = blockIdx.x * 16 + threadIdx.x;
    int i = blockIdx.y * 16 + threadIdx.y;
    float s = sp[0];
    float ga = ea[j] / s, gb = eb[i] / s;
    float ga2 = ga * ga + 1.f, gb2 = gb * gb + 1.f;
    float mre = gb / gb2 - ga / ga2;
    float mim = 1.f / gb2 - 1.f / ga2;
    float m = mre * mre + mim * mim;
    maskS[i * KD + j] = m;
    maskS[KK + j * KD + i] = m;
}

// Gram GEMMs (TN, fp32): z=0: G_a=A^T A ; z=1: G_b=B^T B ; z=2: Bvec_top = B^T A
__global__ __launch_bounds__(256, 2)
void gemm_tn(const float* __restrict__ A, const float* __restrict__ Bm,
             float* __restrict__ G, float* __restrict__ Bv) {
    int z = blockIdx.z;
    const float* M1 = (z == 0) ? A : Bm;
    const float* M2 = (z == 1) ? Bm : A;
    float* O = (z == 0) ? G : ((z == 1) ? (G + KK) : Bv);

    __shared__ float As[16][64];
    __shared__ float Bs[16][64];
    int row0 = blockIdx.y * 64, col0 = blockIdx.x * 64;
    int t = threadIdx.x, tx = t & 15, ty = t >> 4;
    float acc[4][4] = {};

    for (int k0 = 0; k0 < DD; k0 += 16) {
#pragma unroll
        for (int i = 0; i < 4; i++) {
            int idx = t + i * 256;
            int m = idx & 63, kk = idx >> 6;
            As[kk][m] = M1[(k0 + kk) * KD + row0 + m];
            Bs[kk][m] = M2[(k0 + kk) * KD + col0 + m];
        }
        __syncthreads();
#pragma unroll
        for (int kk = 0; kk < 16; kk++) {
            float4 a = *(const float4*)&As[kk][ty * 4];
            float4 b = *(const float4*)&Bs[kk][tx * 4];
            acc[0][0] += a.x * b.x; acc[0][1] += a.x * b.y; acc[0][2] += a.x * b.z; acc[0][3] += a.x * b.w;
            acc[1][0] += a.y * b.x; acc[1][1] += a.y * b.y; acc[1][2] += a.y * b.z; acc[1][3] += a.y * b.w;
            acc[2][0] += a.z * b.x; acc[2][1] += a.z * b.y; acc[2][2] += a.z * b.z; acc[2][3] += a.z * b.w;
            acc[3][0] += a.w * b.x; acc[3][1] += a.w * b.y; acc[3][2] += a.w * b.z; acc[3][3] += a.w * b.w;
        }
        __syncthreads();
    }
    int r = row0 + ty * 4, c = col0 + tx * 4;
#pragma unroll
    for (int i = 0; i < 4; i++) {
        float4 o = make_float4(acc[i][0], acc[i][1], acc[i][2], acc[i][3]);
        *(float4*)&O[(r + i) * KD + c] = o;
    }
}

__global__ void k_transB(float* __restrict__ Bv) {
    __shared__ float tile[32][33];
    int bx = blockIdx.x * 32, by = blockIdx.y * 32;
    int tx = threadIdx.x, ty = threadIdx.y;
#pragma unroll
    for (int i = 0; i < 32; i += 8)
        tile[ty + i][tx] = Bv[(by + ty + i) * KD + bx + tx];
    __syncthreads();
#pragma unroll
    for (int i = 0; i < 32; i += 8)
        Bv[(KD + bx + ty + i) * KD + by + tx] = tile[tx][ty + i];
}

__global__ void k_diag(const float* __restrict__ G, float* __restrict__ dg) {
    int idx = blockIdx.x * 256 + threadIdx.x;
    int d = idx >> 9, j = idx & (KD - 1);
    dg[idx] = G[d * KK + j * KD + j];
}

// G fp32 -> split bf16 (hi + lo)
__global__ void k_convG(const float* __restrict__ G, __nv_bfloat16* __restrict__ Gh,
                        __nv_bfloat16* __restrict__ Gl) {
    int i4 = (blockIdx.x * 256 + threadIdx.x) * 4;
    float4 g = *(const float4*)&G[i4];
    __nv_bfloat162 h0, h1, l0, l1;
    h0.x = __float2bfloat16(g.x); h0.y = __float2bfloat16(g.y);
    h1.x = __float2bfloat16(g.z); h1.y = __float2bfloat16(g.w);
    l0.x = __float2bfloat16(g.x - __bfloat162float(h0.x));
    l0.y = __float2bfloat16(g.y - __bfloat162float(h0.y));
    l1.x = __float2bfloat16(g.z - __bfloat162float(h1.x));
    l1.y = __float2bfloat16(g.w - __bfloat162float(h1.y));
    ((__nv_bfloat162*)(Gh + i4))[0] = h0;
    ((__nv_bfloat162*)(Gh + i4))[1] = h1;
    ((__nv_bfloat162*)(Gl + i4))[0] = l0;
    ((__nv_bfloat162*)(Gl + i4))[1] = l1;
}

// ---------------------------------------------------------------------------
// bf16 mma.sync matvec partials: Wp[z] = Az @ Bz^T  (G symmetric → B rows = G rows)
//   z=0: Phi @ Ghi_d ; z=1: Phi @ Glo_d ; z=2: Plo @ Ghi_d
// Tile 64(m) x 64(n), BK=64, double-buffered; 8 warps = 2m x 4n, warp 32x16.
#define PADB 144   // 72 bf16 row stride in bytes
#define STG  9216  // bytes per smem stage buffer (64*144)

__global__ __launch_bounds__(256, 1)
void gemm_bf16(const __nv_bfloat16* __restrict__ Ph, const __nv_bfloat16* __restrict__ Pl,
               const __nv_bfloat16* __restrict__ Gh, const __nv_bfloat16* __restrict__ Gl,
               float* __restrict__ Wp) {
    __shared__ __align__(128) char sA[2 * STG];
    __shared__ __align__(128) char sB[2 * STG];
    int z = blockIdx.z;
    int r0 = blockIdx.y * 64, c0 = blockIdx.x * 64;
    const __nv_bfloat16* Asrc = (z == 2) ? Pl : Ph;
    const __nv_bfloat16* Bsrc = ((z == 1) ? Gl : Gh) + ((r0 >= KD) ? (size_t)KK : 0);
    float* Out = Wp + (size_t)z * U2;

    int t = threadIdx.x;
    int lane = t & 31, w = t >> 5;
    int wm = w >> 2, wn = w & 3;           // 2m x 4n warps
    int lrow = t >> 3, lkb = t & 7;        // loaders: 32 rows/pass, 8 bf16 chunks

    uint32_t sa = smem_u32(sA), sbm = smem_u32(sB);
    uint32_t aBase = sa + (uint32_t)(wm * 32 + (lane & 15)) * PADB + (lane >> 4) * 16;
    uint32_t bBase = sbm + (uint32_t)(wn * 16 + (lane & 15)) * PADB + (lane >> 4) * 16;

    float acc[2][2][4] = {};
    float4 va[2], vb[2];

    // prologue: stage 0
#pragma unroll
    for (int i = 0; i < 2; i++) {
        va[i] = *(const float4*)(Asrc + (size_t)(r0 + lrow + i * 32) * KD + lkb * 8);
        vb[i] = *(const float4*)(Bsrc + (size_t)(c0 + lrow + i * 32) * KD + lkb * 8);
    }
#pragma unroll
    for (int i = 0; i < 2; i++) {
        *(float4*)(sA + (lrow + i * 32) * PADB + lkb * 16) = va[i];
        *(float4*)(sB + (lrow + i * 32) * PADB + lkb * 16) = vb[i];
    }
    __syncthreads();

#pragma unroll 1
    for (int s = 0; s < 8; s++) {
        int buf = s & 1;
        if (s + 1 < 8) {
            int k0 = (s + 1) * 64;
#pragma unroll
            for (int i = 0; i < 2; i++) {
                va[i] = *(const float4*)(Asrc + (size_t)(r0 + lrow + i * 32) * KD + k0 + lkb * 8);
                vb[i] = *(const float4*)(Bsrc + (size_t)(c0 + lrow + i * 32) * KD + k0 + lkb * 8);
            }
        }
#pragma unroll
        for (int kk = 0; kk < 4; kk++) {
            uint32_t b0, b1, b2, b3;
            LDSM4(b0, b1, b2, b3, bBase + buf * STG + kk * 32);
#pragma unroll
            for (int tm = 0; tm < 2; tm++) {
                uint32_t a0, a1, a2, a3;
                LDSM4(a0, a1, a2, a3, aBase + buf * STG + kk * 32 + tm * 16 * PADB);
                mma16816(acc[tm][0], a0, a1, a2, a3, b0, b2);
                mma16816(acc[tm][1], a0, a1, a2, a3, b1, b3);
            }
        }
        __syncthreads();
        if (s + 1 < 8) {
            int nb = buf ^ 1;
#pragma unroll
            for (int i = 0; i < 2; i++) {
                *(float4*)(sA + nb * STG + (lrow + i * 32) * PADB + lkb * 16) = va[i];
                *(float4*)(sB + nb * STG + (lrow + i * 32) * PADB + lkb * 16) = vb[i];
            }
            __syncthreads();
        }
    }

    // epilogue: c layout of m16n8: rows q, q+8; cols 2*(lane&3)
    int q = lane >> 2, cc = (lane & 3) * 2;
#pragma unroll
    for (int tm = 0; tm < 2; tm++)
#pragma unroll
        for (int tn = 0; tn < 2; tn++) {
            float* dst = Out + (size_t)(r0 + wm * 32 + tm * 16 + q) * KD
                             + (c0 + wn * 16 + tn * 8 + cc);
            *(float2*)dst = make_float2(acc[tm][tn][0], acc[tm][tn][1]);
            *(float2*)(dst + 8 * KD) = make_float2(acc[tm][tn][2], acc[tm][tn][3]);
        }
}

// ---------------------------------------------------------------------------
// fp32 split-K GEMM (polish iterations): Wp[z] partial over K-chunk z (4 chunks)
__global__ __launch_bounds__(256, 1)
void gemm_nn_sk(const float* __restrict__ L, const float* __restrict__ Ga,
                const float* __restrict__ Gb, float* __restrict__ Wp) {
    __shared__ float Ls[2][8][128];
    __shared__ float Rs[2][8][128];
    int r0 = blockIdx.y * 128, c0 = blockIdx.x * 128;
    int kbase = blockIdx.z * 128;
    const float* Rm = (r0 < KD) ? Ga : Gb;
    float* Out = Wp + (size_t)blockIdx.z * U2;

    int t = threadIdx.x;
    int tx = t & 15, ty = t >> 4;
    int lm = t >> 1, lk4 = (t & 1) * 4;
    int rk = t >> 5, rc4 = (t & 31) * 4;

    float acc[8][8] = {};

    float4 lv = *(const float4*)&L[(size_t)(r0 + lm) * KD + kbase + lk4];
    float4 rv = *(const float4*)&Rm[(size_t)(kbase + rk) * KD + c0 + rc4];
    Ls[0][lk4 + 0][lm] = lv.x; Ls[0][lk4 + 1][lm] = lv.y;
    Ls[0][lk4 + 2][lm] = lv.z; Ls[0][lk4 + 3][lm] = lv.w;
    *(float4*)&Rs[0][rk][rc4] = rv;
    __syncthreads();

    int buf = 0;
#pragma unroll 1
    for (int ks = 0; ks < 16; ks++) {
        if (ks + 1 < 16) {
            int k0 = kbase + (ks + 1) * 8;
            lv = *(const float4*)&L[(size_t)(r0 + lm) * KD + k0 + lk4];
            rv = *(const float4*)&Rm[(size_t)(k0 + rk) * KD + c0 + rc4];
        }
#pragma unroll
        for (int kk = 0; kk < 8; kk++) {
            float a[8], b[8];
            *(float4*)&a[0] = *(const float4*)&Ls[buf][kk][ty * 8];
            *(float4*)&a[4] = *(const float4*)&Ls[buf][kk][ty * 8 + 4];
            *(float4*)&b[0] = *(const float4*)&Rs[buf][kk][tx * 8];
            *(float4*)&b[4] = *(const float4*)&Rs[buf][kk][tx * 8 + 4];
#pragma unroll
            for (int i = 0; i < 8; i++)
#pragma unroll
                for (int j = 0; j < 8; j++) acc[i][j] += a[i] * b[j];
        }
        if (ks + 1 < 16) {
            int nb = buf ^ 1;
            Ls[nb][lk4 + 0][lm] = lv.x; Ls[nb][lk4 + 1][lm] = lv.y;
            Ls[nb][lk4 + 2][lm] = lv.z; Ls[nb][lk4 + 3][lm] = lv.w;
            *(float4*)&Rs[nb][rk][rc4] = rv;
            __syncthreads();
            buf = nb;
        }
    }

#pragma unroll
    for (int i = 0; i < 8; i++) {
        size_t off = (size_t)(r0 + ty * 8 + i) * KD + c0 + tx * 8;
        *(float4*)&Out[off]     = make_float4(acc[i][0], acc[i][1], acc[i][2], acc[i][3]);
        *(float4*)&Out[off + 4] = make_float4(acc[i][4], acc[i][5], acc[i][6], acc[i][7]);
    }
}

// ---------------------------------------------------------------------------
__device__ __forceinline__ float rowReduce(float v, float* sm, int t) {
#pragma unroll
    for (int o = 16; o; o >>= 1) v += __shfl_xor_sync(0xffffffffu, v, o);
    if ((t & 31) == 0) sm[t >> 5] = v;
    __syncthreads();
    return sm[0] + sm[1] + sm[2] + sm[3];
}

__device__ __forceinline__ void splitStore(__nv_bfloat16* Ph, __nv_bfloat16* Pl,
                                           int off, float4 p) {
    __nv_bfloat162 h0, h1, l0, l1;
    h0.x = __float2bfloat16(p.x); h0.y = __float2bfloat16(p.y);
    h1.x = __float2bfloat16(p.z); h1.y = __float2bfloat16(p.w);
    l0.x = __float2bfloat16(p.x - __bfloat162float(h0.x));
    l0.y = __float2bfloat16(p.y - __bfloat162float(h0.y));
    l1.x = __float2bfloat16(p.z - __bfloat162float(h1.x));
    l1.y = __float2bfloat16(p.w - __bfloat162float(h1.y));
    ((__nv_bfloat162*)(Ph + off))[0] = h0;
    ((__nv_bfloat162*)(Ph + off))[1] = h1;
    ((__nv_bfloat162*)(Pl + off))[0] = l0;
    ((__nv_bfloat162*)(Pl + off))[1] = l1;
}

// x=0, r=b, z=r/d, p=z (+ bf16 split of p), rho=r.z
__global__ void k_cg_init(const float* __restrict__ Bv, float* __restrict__ X,
                          float* __restrict__ R, float* __restrict__ P,
                          const float* __restrict__ mask, const float* __restrict__ dg,
                          float* __restrict__ rho,
                          __nv_bfloat16* __restrict__ Ph, __nv_bfloat16* __restrict__ Pl) {
    __shared__ float s1[4];
    int r = blockIdx.x, t = threadIdx.x;
    int off = r * KD + t * 4;
    float4 b = *(const float4*)&Bv[off];
    float4 m = *(const float4*)&mask[off];
    float4 dv = *(const float4*)&dg[((r >> 9) << 9) + t * 4];
    float4 z;
    z.x = b.x / (dv.x + LMB * m.x);
    z.y = b.y / (dv.y + LMB * m.y);
    z.z = b.z / (dv.z + LMB * m.z);
    z.w = b.w / (dv.w + LMB * m.w);
    float rz = b.x * z.x + b.y * z.y + b.z * z.z + b.w * z.w;
    rz = rowReduce(rz, s1, t);
    *(float4*)&X[off] = make_float4(0.f, 0.f, 0.f, 0.f);
    *(float4*)&R[off] = b;
    *(float4*)&P[off] = z;
    splitStore(Ph, Pl, off, z);
    if (t == 0) rho[r] = rz;
}

// w = sum_{z<np} Wp[z] + lmbda*m.*p; standard PCG step; p split to bf16
__global__ void k_cg_step(float* __restrict__ X, float* __restrict__ R,
                          float* __restrict__ P, const float* __restrict__ Wp,
                          const float* __restrict__ mask, const float* __restrict__ dg,
                          float* __restrict__ rho,
                          __nv_bfloat16* __restrict__ Ph, __nv_bfloat16* __restrict__ Pl,
                          int np) {
    __shared__ float s1[4], s2[4];
    int r = blockIdx.x, t = threadIdx.x;
    int off = r * KD + t * 4;
    float4 p  = *(const float4*)&P[off];
    float4 m  = *(const float4*)&mask[off];
    float4 dv = *(const float4*)&dg[((r >> 9) << 9) + t * 4];
    float4 w = make_float4(LMB * m.x * p.x, LMB * m.y * p.y,
                           LMB * m.z * p.z, LMB * m.w * p.w);
    for (int z = 0; z < np; z++) {
        float4 wz = *(const float4*)&Wp[(size_t)z * U2 + off];
        w.x += wz.x; w.y += wz.y; w.z += wz.z; w.w += wz.w;
    }

    float pq = p.x * w.x + p.y * w.y + p.z * w.z + p.w * w.w;
    pq = rowReduce(pq, s1, t);
    float rho_old = rho[r];
    float al = rho_old / (pq + 1e-30f);

    float4 x = *(float4*)&X[off];
    float4 rv = *(float4*)&R[off];
    x.x += al * p.x; x.y += al * p.y; x.z += al * p.z; x.w += al * p.w;
    rv.x -= al * w.x; rv.y -= al * w.y; rv.z -= al * w.z; rv.w -= al * w.w;

    float4 z4;
    z4.x = rv.x / (dv.x + LMB * m.x);
    z4.y = rv.y / (dv.y + LMB * m.y);
    z4.z = rv.z / (dv.z + LMB * m.z);
    z4.w = rv.w / (dv.w + LMB * m.w);
    float rz = rv.x * z4.x + rv.y * z4.y + rv.z * z4.z + rv.w * z4.w;
    __syncthreads();
    rz = rowReduce(rz, s2, t);
    float be = rz / (rho_old > 0.f ? rho_old + 1e-30f : (rho_old - 1e-30f));

    p.x = z4.x + be * p.x; p.y = z4.y + be * p.y;
    p.z = z4.z + be * p.z; p.w = z4.w + be * p.w;

    *(float4*)&X[off] = x;
    *(float4*)&R[off] = rv;
    *(float4*)&P[off] = p;
    splitStore(Ph, Pl, off, p);
    if (t == 0) rho[r] = rz;
}

// ---------------------------------------------------------------------------
extern "C" void kernel_launch(void* const* d_in, const int* in_sizes, int n_in,
                              void* d_out, int out_size) {
    (void)in_sizes; (void)n_in; (void)out_size;
    const float* A  = (const float*)d_in[0];
    const float* Bm = (const float*)d_in[1];
    const float* ea = (const float*)d_in[2];
    const float* eb = (const float*)d_in[3];
    float* X = (float*)d_out;

    float* S = nullptr;
    cudaGetSymbolAddress((void**)&S, g_scratch);
    float* G    = S;
    float* mask = S + 1ull * U2;
    float* Bv   = S + 2ull * U2;
    float* R    = S + 3ull * U2;
    float* P    = S + 4ull * U2;
    float* W    = S + 5ull * U2;     // 4 partial buffers -> through 9*U2
    __nv_bfloat16* Gh  = (__nv_bfloat16*)(S + 9ull * U2);
    __nv_bfloat16* Gl  = Gh + U2;
    __nv_bfloat16* Pbh = Gl + U2;
    __nv_bfloat16* Pbl = Pbh + U2;   // bf16 block = 2*U2 floats -> ends at 11*U2
    float* dg  = S + 11ull * U2;
    float* rho = dg + 1024;
    float* sp  = rho + 1024;

    k_prep<<<1, 512>>>(ea, eb, sp);
    k_mask<<<dim3(KD / 16, KD / 16), dim3(16, 16)>>>(ea, eb, sp, mask);
    gemm_tn<<<dim3(8, 8, 3), 256>>>(A, Bm, G, Bv);
    k_transB<<<dim3(16, 16), dim3(32, 8)>>>(Bv);
    k_diag<<<4, 256>>>(G, dg);
    k_convG<<<U2 / 1024, 256>>>(G, Gh, Gl);
    k_cg_init<<<1024, 128>>>(Bv, X, R, P, mask, dg, rho, Pbh, Pbl);

    for (int i = 0; i < ITERS_BF16; i++) {
        gemm_bf16<<<dim3(8, 16, 3), 256>>>(Pbh, Pbl, Gh, Gl, W);
        k_cg_step<<<1024, 128>>>(X, R, P, W, mask, dg, rho, Pbh, Pbl, 3);
    }
    for (int i = 0; i < ITERS_F32; i++) {
        gemm_nn_sk<<<dim3(4, 8, 4), 256>>>(P, G, G + KK, W);
        k_cg_step<<<1024, 128>>>(X, R, P, W, mask, dg, rho, Pbh, Pbl, 4);
    }
}

// round 14
// speedup vs baseline: 4.0194x; 1.8095x over previous
#include <cuda_runtime.h>
#include <cuda_bf16.h>
#include <cstdint>

#define KD 512
#define DD 1024
#define KK (KD*KD)
#define U2 (2*KK)
#define LMB 1000.0f
#define ITERS_BF16 20
#define ITERS_F32  2

__device__ __align__(128) float g_scratch[13ull*U2 + 4096];

// ---------------------------------------------------------------------------
__device__ __forceinline__ uint32_t smem_u32(const void* p) {
    uint32_t a;
    asm("{ .reg .u64 t; cvta.to.shared.u64 t, %1; cvt.u32.u64 %0, t; }" : "=r"(a) : "l"(p));
    return a;
}
#define LDSM4(r0, r1, r2, r3, addr)                                         \
    asm volatile("ldmatrix.sync.aligned.m8n8.x4.shared.b16 {%0,%1,%2,%3}, [%4];" \
                 : "=r"(r0), "=r"(r1), "=r"(r2), "=r"(r3) : "r"(addr))

__device__ __forceinline__ void mma16816(float* c, uint32_t a0, uint32_t a1,
                                         uint32_t a2, uint32_t a3,
                                         uint32_t b0, uint32_t b1) {
    asm volatile("mma.sync.aligned.m16n8k16.row.col.f32.bf16.bf16.f32 "
                 "{%0,%1,%2,%3},{%4,%5,%6,%7},{%8,%9},{%0,%1,%2,%3};"
                 : "+f"(c[0]), "+f"(c[1]), "+f"(c[2]), "+f"(c[3])
                 : "r"(a0), "r"(a1), "r"(a2), "r"(a3), "r"(b0), "r"(b1));
}

#define SWZ(bo) ((bo) ^ (((bo) >> 3) & 0x70))

// ---------------------------------------------------------------------------
__global__ void k_prep(const float* __restrict__ ea, const float* __restrict__ eb,
                       float* __restrict__ sp) {
    __shared__ float sm[512];
    int t = threadIdx.x;
    sm[t] = fmaxf(ea[t], eb[t]);
    __syncthreads();
    for (int s = 256; s; s >>= 1) {
        if (t < s) sm[t] = fmaxf(sm[t], sm[t + s]);
        __syncthreads();
    }
    if (t == 0) sp[0] = sm[0];
}

__global__ void k_mask(const float* __restrict__ ea, const float* __restrict__ eb,
                       const float* __restrict__ sp, float* __restrict__ maskS) {
    int j = blockIdx.x * 16 + threadIdx.x;
    int i = blockIdx.y * 16 + threadIdx.y;
    float s = sp[0];
    float ga = ea[j] / s, gb = eb[i] / s;
    float ga2 = ga * ga + 1.f, gb2 = gb * gb + 1.f;
    float mre = gb / gb2 - ga / ga2;
    float mim = 1.f / gb2 - 1.f / ga2;
    float m = mre * mre + mim * mim;
    maskS[i * KD + j] = m;
    maskS[KK + j * KD + i] = m;
}

// Gram GEMMs (TN, fp32): z=0: G_a=A^T A ; z=1: G_b=B^T B ; z=2: Bvec_top = B^T A
__global__ __launch_bounds__(256, 2)
void gemm_tn(const float* __restrict__ A, const float* __restrict__ Bm,
             float* __restrict__ G, float* __restrict__ Bv) {
    int z = blockIdx.z;
    const float* M1 = (z == 0) ? A : Bm;
    const float* M2 = (z == 1) ? Bm : A;
    float* O = (z == 0) ? G : ((z == 1) ? (G + KK) : Bv);

    __shared__ float As[16][64];
    __shared__ float Bs[16][64];
    int row0 = blockIdx.y * 64, col0 = blockIdx.x * 64;
    int t = threadIdx.x, tx = t & 15, ty = t >> 4;
    float acc[4][4] = {};

    for (int k0 = 0; k0 < DD; k0 += 16) {
#pragma unroll
        for (int i = 0; i < 4; i++) {
            int idx = t + i * 256;
            int m = idx & 63, kk = idx >> 6;
            As[kk][m] = M1[(k0 + kk) * KD + row0 + m];
            Bs[kk][m] = M2[(k0 + kk) * KD + col0 + m];
        }
        __syncthreads();
#pragma unroll
        for (int kk = 0; kk < 16; kk++) {
            float4 a = *(const float4*)&As[kk][ty * 4];
            float4 b = *(const float4*)&Bs[kk][tx * 4];
            acc[0][0] += a.x * b.x; acc[0][1] += a.x * b.y; acc[0][2] += a.x * b.z; acc[0][3] += a.x * b.w;
            acc[1][0] += a.y * b.x; acc[1][1] += a.y * b.y; acc[1][2] += a.y * b.z; acc[1][3] += a.y * b.w;
            acc[2][0] += a.z * b.x; acc[2][1] += a.z * b.y; acc[2][2] += a.z * b.z; acc[2][3] += a.z * b.w;
            acc[3][0] += a.w * b.x; acc[3][1] += a.w * b.y; acc[3][2] += a.w * b.z; acc[3][3] += a.w * b.w;
        }
        __syncthreads();
    }
    int r = row0 + ty * 4, c = col0 + tx * 4;
#pragma unroll
    for (int i = 0; i < 4; i++) {
        float4 o = make_float4(acc[i][0], acc[i][1], acc[i][2], acc[i][3]);
        *(float4*)&O[(r + i) * KD + c] = o;
    }
}

__global__ void k_transB(float* __restrict__ Bv) {
    __shared__ float tile[32][33];
    int bx = blockIdx.x * 32, by = blockIdx.y * 32;
    int tx = threadIdx.x, ty = threadIdx.y;
#pragma unroll
    for (int i = 0; i < 32; i += 8)
        tile[ty + i][tx] = Bv[(by + ty + i) * KD + bx + tx];
    __syncthreads();
#pragma unroll
    for (int i = 0; i < 32; i += 8)
        Bv[(KD + bx + ty + i) * KD + by + tx] = tile[tx][ty + i];
}

__global__ void k_diag(const float* __restrict__ G, float* __restrict__ dg) {
    int idx = blockIdx.x * 256 + threadIdx.x;
    int d = idx >> 9, j = idx & (KD - 1);
    dg[idx] = G[d * KK + j * KD + j];
}

// G fp32 -> split bf16 (hi + lo)
__global__ void k_convG(const float* __restrict__ G, __nv_bfloat16* __restrict__ Gh,
                        __nv_bfloat16* __restrict__ Gl) {
    int i4 = (blockIdx.x * 256 + threadIdx.x) * 4;
    float4 g = *(const float4*)&G[i4];
    __nv_bfloat162 h0, h1, l0, l1;
    h0.x = __float2bfloat16(g.x); h0.y = __float2bfloat16(g.y);
    h1.x = __float2bfloat16(g.z); h1.y = __float2bfloat16(g.w);
    l0.x = __float2bfloat16(g.x - __bfloat162float(h0.x));
    l0.y = __float2bfloat16(g.y - __bfloat162float(h0.y));
    l1.x = __float2bfloat16(g.z - __bfloat162float(h1.x));
    l1.y = __float2bfloat16(g.w - __bfloat162float(h1.y));
    ((__nv_bfloat162*)(Gh + i4))[0] = h0;
    ((__nv_bfloat162*)(Gh + i4))[1] = h1;
    ((__nv_bfloat162*)(Gl + i4))[0] = l0;
    ((__nv_bfloat162*)(Gl + i4))[1] = l1;
}

// ---------------------------------------------------------------------------
// bf16 mma.sync matvec partials, v2:
//   products: p=0: Phi@Ghi ; p=1: Phi@Glo ; p=2: Plo@Ghi   (G symmetric)
//   z = p*2 + kchunk : split-K=2 (Kc=256). Wp[z] = partial.
// CTA tile 128x128, warp tile 64x32 (2m x 4n warps), BK=64, double buffered.
// SMEM: SW128 swizzle on compact 128-byte rows; 64KB dynamic.
#define NSTG 4          // 256 / 64
#define STGB 16384      // bytes per operand stage: 128 rows * 128B

__global__ __launch_bounds__(256)
void gemm_bf16(const __nv_bfloat16* __restrict__ Ph, const __nv_bfloat16* __restrict__ Pl,
               const __nv_bfloat16* __restrict__ Gh, const __nv_bfloat16* __restrict__ Gl,
               float* __restrict__ Wp) {
    extern __shared__ __align__(128) char smem[];   // [A0 A1 B0 B1] 4*16KB
    char* sA = smem;
    char* sB = smem + 2 * STGB;

    int z = blockIdx.z;
    int prod = z >> 1;
    int kc = (z & 1) * 256;
    int r0 = blockIdx.y * 128, c0 = blockIdx.x * 128;
    const __nv_bfloat16* Asrc = (prod == 2) ? Pl : Ph;
    const __nv_bfloat16* Bsrc = ((prod == 1) ? Gl : Gh) + ((r0 >= KD) ? (size_t)KK : 0);
    float* Out = Wp + (size_t)z * U2;

    int t = threadIdx.x;
    int lane = t & 31, w = t >> 5;
    int wm = w >> 2, wn = w & 3;          // 2m x 4n warps -> 64x32 per warp
    int lrow = t >> 3, lch = t & 7;       // loader: 32 rows/pass, 8x16B chunks/row

    uint32_t sa = smem_u32(sA), sb = smem_u32(sB);
    // ldmatrix lane address components
    int lrA = (lane & 15), lcA = (lane >> 4) * 16;

    float acc[4][4][4] = {};
    float4 va[4], vb[4];

    // prologue: stage 0
#pragma unroll
    for (int i = 0; i < 4; i++) {
        int row = lrow + i * 32;
        va[i] = *(const float4*)(Asrc + (size_t)(r0 + row) * KD + kc + lch * 8);
        vb[i] = *(const float4*)(Bsrc + (size_t)(c0 + row) * KD + kc + lch * 8);
    }
#pragma unroll
    for (int i = 0; i < 4; i++) {
        int row = lrow + i * 32;
        uint32_t bo = SWZ((uint32_t)(row * 128 + lch * 16));
        *(float4*)(sA + bo) = va[i];
        *(float4*)(sB + bo) = vb[i];
    }
    __syncthreads();

#pragma unroll 1
    for (int s = 0; s < NSTG; s++) {
        int buf = s & 1;
        if (s + 1 < NSTG) {
            int k0 = kc + (s + 1) * 64;
#pragma unroll
            for (int i = 0; i < 4; i++) {
                int row = lrow + i * 32;
                va[i] = *(const float4*)(Asrc + (size_t)(r0 + row) * KD + k0 + lch * 8);
                vb[i] = *(const float4*)(Bsrc + (size_t)(c0 + row) * KD + k0 + lch * 8);
            }
        }
        uint32_t saB = sa + buf * STGB, sbB = sb + buf * STGB;
#pragma unroll
        for (int kk = 0; kk < 4; kk++) {
            uint32_t bb[2][4];
#pragma unroll
            for (int tn2 = 0; tn2 < 2; tn2++) {
                int rowB = wn * 32 + tn2 * 16 + lrA;
                uint32_t adr = sbB + SWZ((uint32_t)(rowB * 128 + kk * 32 + lcA));
                LDSM4(bb[tn2][0], bb[tn2][1], bb[tn2][2], bb[tn2][3], adr);
            }
#pragma unroll
            for (int tm = 0; tm < 4; tm++) {
                int rowA = wm * 64 + tm * 16 + lrA;
                uint32_t adr = saB + SWZ((uint32_t)(rowA * 128 + kk * 32 + lcA));
                uint32_t a0, a1, a2, a3;
                LDSM4(a0, a1, a2, a3, adr);
                mma16816(acc[tm][0], a0, a1, a2, a3, bb[0][0], bb[0][2]);
                mma16816(acc[tm][1], a0, a1, a2, a3, bb[0][1], bb[0][3]);
                mma16816(acc[tm][2], a0, a1, a2, a3, bb[1][0], bb[1][2]);
                mma16816(acc[tm][3], a0, a1, a2, a3, bb[1][1], bb[1][3]);
            }
        }
        __syncthreads();
        if (s + 1 < NSTG) {
            int nb = (buf ^ 1) * STGB;
#pragma unroll
            for (int i = 0; i < 4; i++) {
                int row = lrow + i * 32;
                uint32_t bo = SWZ((uint32_t)(row * 128 + lch * 16));
                *(float4*)(sA + nb + bo) = va[i];
                *(float4*)(sB + nb + bo) = vb[i];
            }
            __syncthreads();
        }
    }

    // epilogue: m16n8 acc layout: rows q, q+8; cols 2*(lane&3)
    int q = lane >> 2, cc = (lane & 3) * 2;
#pragma unroll
    for (int tm = 0; tm < 4; tm++)
#pragma unroll
        for (int tn = 0; tn < 4; tn++) {
            float* dst = Out + (size_t)(r0 + wm * 64 + tm * 16 + q) * KD
                             + (c0 + wn * 32 + tn * 8 + cc);
            *(float2*)dst = make_float2(acc[tm][tn][0], acc[tm][tn][1]);
            *(float2*)(dst + 8 * KD) = make_float2(acc[tm][tn][2], acc[tm][tn][3]);
        }
}

// ---------------------------------------------------------------------------
// fp32 split-K GEMM (polish iterations): Wp[z] partial over K-chunk z (4 chunks)
__global__ __launch_bounds__(256, 1)
void gemm_nn_sk(const float* __restrict__ L, const float* __restrict__ Ga,
                const float* __restrict__ Gb, float* __restrict__ Wp) {
    __shared__ float Ls[2][8][128];
    __shared__ float Rs[2][8][128];
    int r0 = blockIdx.y * 128, c0 = blockIdx.x * 128;
    int kbase = blockIdx.z * 128;
    const float* Rm = (r0 < KD) ? Ga : Gb;
    float* Out = Wp + (size_t)blockIdx.z * U2;

    int t = threadIdx.x;
    int tx = t & 15, ty = t >> 4;
    int lm = t >> 1, lk4 = (t & 1) * 4;
    int rk = t >> 5, rc4 = (t & 31) * 4;

    float acc[8][8] = {};

    float4 lv = *(const float4*)&L[(size_t)(r0 + lm) * KD + kbase + lk4];
    float4 rv = *(const float4*)&Rm[(size_t)(kbase + rk) * KD + c0 + rc4];
    Ls[0][lk4 + 0][lm] = lv.x; Ls[0][lk4 + 1][lm] = lv.y;
    Ls[0][lk4 + 2][lm] = lv.z; Ls[0][lk4 + 3][lm] = lv.w;
    *(float4*)&Rs[0][rk][rc4] = rv;
    __syncthreads();

    int buf = 0;
#pragma unroll 1
    for (int ks = 0; ks < 16; ks++) {
        if (ks + 1 < 16) {
            int k0 = kbase + (ks + 1) * 8;
            lv = *(const float4*)&L[(size_t)(r0 + lm) * KD + k0 + lk4];
            rv = *(const float4*)&Rm[(size_t)(k0 + rk) * KD + c0 + rc4];
        }
#pragma unroll
        for (int kk = 0; kk < 8; kk++) {
            float a[8], b[8];
            *(float4*)&a[0] = *(const float4*)&Ls[buf][kk][ty * 8];
            *(float4*)&a[4] = *(const float4*)&Ls[buf][kk][ty * 8 + 4];
            *(float4*)&b[0] = *(const float4*)&Rs[buf][kk][tx * 8];
            *(float4*)&b[4] = *(const float4*)&Rs[buf][kk][tx * 8 + 4];
#pragma unroll
            for (int i = 0; i < 8; i++)
#pragma unroll
                for (int j = 0; j < 8; j++) acc[i][j] += a[i] * b[j];
        }
        if (ks + 1 < 16) {
            int nb = buf ^ 1;
            Ls[nb][lk4 + 0][lm] = lv.x; Ls[nb][lk4 + 1][lm] = lv.y;
            Ls[nb][lk4 + 2][lm] = lv.z; Ls[nb][lk4 + 3][lm] = lv.w;
            *(float4*)&Rs[nb][rk][rc4] = rv;
            __syncthreads();
            buf = nb;
        }
    }

#pragma unroll
    for (int i = 0; i < 8; i++) {
        size_t off = (size_t)(r0 + ty * 8 + i) * KD + c0 + tx * 8;
        *(float4*)&Out[off]     = make_float4(acc[i][0], acc[i][1], acc[i][2], acc[i][3]);
        *(float4*)&Out[off + 4] = make_float4(acc[i][4], acc[i][5], acc[i][6], acc[i][7]);
    }
}

// ---------------------------------------------------------------------------
__device__ __forceinline__ float rowReduce(float v, float* sm, int t) {
#pragma unroll
    for (int o = 16; o; o >>= 1) v += __shfl_xor_sync(0xffffffffu, v, o);
    if ((t & 31) == 0) sm[t >> 5] = v;
    __syncthreads();
    return sm[0] + sm[1] + sm[2] + sm[3];
}

__device__ __forceinline__ void splitStore(__nv_bfloat16* Ph, __nv_bfloat16* Pl,
                                           int off, float4 p) {
    __nv_bfloat162 h0, h1, l0, l1;
    h0.x = __float2bfloat16(p.x); h0.y = __float2bfloat16(p.y);
    h1.x = __float2bfloat16(p.z); h1.y = __float2bfloat16(p.w);
    l0.x = __float2bfloat16(p.x - __bfloat162float(h0.x));
    l0.y = __float2bfloat16(p.y - __bfloat162float(h0.y));
    l1.x = __float2bfloat16(p.z - __bfloat162float(h1.x));
    l1.y = __float2bfloat16(p.w - __bfloat162float(h1.y));
    ((__nv_bfloat162*)(Ph + off))[0] = h0;
    ((__nv_bfloat162*)(Ph + off))[1] = h1;
    ((__nv_bfloat162*)(Pl + off))[0] = l0;
    ((__nv_bfloat162*)(Pl + off))[1] = l1;
}

// x=0, r=b, z=r/d, p=z (+ bf16 split of p), rho=r.z
__global__ void k_cg_init(const float* __restrict__ Bv, float* __restrict__ X,
                          float* __restrict__ R, float* __restrict__ P,
                          const float* __restrict__ mask, const float* __restrict__ dg,
                          float* __restrict__ rho,
                          __nv_bfloat16* __restrict__ Ph, __nv_bfloat16* __restrict__ Pl) {
    __shared__ float s1[4];
    int r = blockIdx.x, t = threadIdx.x;
    int off = r * KD + t * 4;
    float4 b = *(const float4*)&Bv[off];
    float4 m = *(const float4*)&mask[off];
    float4 dv = *(const float4*)&dg[((r >> 9) << 9) + t * 4];
    float4 z;
    z.x = b.x / (dv.x + LMB * m.x);
    z.y = b.y / (dv.y + LMB * m.y);
    z.z = b.z / (dv.z + LMB * m.z);
    z.w = b.w / (dv.w + LMB * m.w);
    float rz = b.x * z.x + b.y * z.y + b.z * z.z + b.w * z.w;
    rz = rowReduce(rz, s1, t);
    *(float4*)&X[off] = make_float4(0.f, 0.f, 0.f, 0.f);
    *(float4*)&R[off] = b;
    *(float4*)&P[off] = z;
    splitStore(Ph, Pl, off, z);
    if (t == 0) rho[r] = rz;
}

// w = sum_{z<np} Wp[z] + lmbda*m.*p; standard PCG step; p split to bf16
__global__ void k_cg_step(float* __restrict__ X, float* __restrict__ R,
                          float* __restrict__ P, const float* __restrict__ Wp,
                          const float* __restrict__ mask, const float* __restrict__ dg,
                          float* __restrict__ rho,
                          __nv_bfloat16* __restrict__ Ph, __nv_bfloat16* __restrict__ Pl,
                          int np) {
    __shared__ float s1[4], s2[4];
    int r = blockIdx.x, t = threadIdx.x;
    int off = r * KD + t * 4;
    float4 p  = *(const float4*)&P[off];
    float4 m  = *(const float4*)&mask[off];
    float4 dv = *(const float4*)&dg[((r >> 9) << 9) + t * 4];
    float4 w = make_float4(LMB * m.x * p.x, LMB * m.y * p.y,
                           LMB * m.z * p.z, LMB * m.w * p.w);
    for (int z = 0; z < np; z++) {
        float4 wz = *(const float4*)&Wp[(size_t)z * U2 + off];
        w.x += wz.x; w.y += wz.y; w.z += wz.z; w.w += wz.w;
    }

    float pq = p.x * w.x + p.y * w.y + p.z * w.z + p.w * w.w;
    pq = rowReduce(pq, s1, t);
    float rho_old = rho[r];
    float al = rho_old / (pq + 1e-30f);

    float4 x = *(float4*)&X[off];
    float4 rv = *(float4*)&R[off];
    x.x += al * p.x; x.y += al * p.y; x.z += al * p.z; x.w += al * p.w;
    rv.x -= al * w.x; rv.y -= al * w.y; rv.z -= al * w.z; rv.w -= al * w.w;

    float4 z4;
    z4.x = rv.x / (dv.x + LMB * m.x);
    z4.y = rv.y / (dv.y + LMB * m.y);
    z4.z = rv.z / (dv.z + LMB * m.z);
    z4.w = rv.w / (dv.w + LMB * m.w);
    float rz = rv.x * z4.x + rv.y * z4.y + rv.z * z4.z + rv.w * z4.w;
    __syncthreads();
    rz = rowReduce(rz, s2, t);
    float be = rz / (rho_old > 0.f ? rho_old + 1e-30f : (rho_old - 1e-30f));

    p.x = z4.x + be * p.x; p.y = z4.y + be * p.y;
    p.z = z4.z + be * p.z; p.w = z4.w + be * p.w;

    *(float4*)&X[off] = x;
    *(float4*)&R[off] = rv;
    *(float4*)&P[off] = p;
    splitStore(Ph, Pl, off, p);
    if (t == 0) rho[r] = rz;
}

// ---------------------------------------------------------------------------
extern "C" void kernel_launch(void* const* d_in, const int* in_sizes, int n_in,
                              void* d_out, int out_size) {
    (void)in_sizes; (void)n_in; (void)out_size;
    const float* A  = (const float*)d_in[0];
    const float* Bm = (const float*)d_in[1];
    const float* ea = (const float*)d_in[2];
    const float* eb = (const float*)d_in[3];
    float* X = (float*)d_out;

    float* S = nullptr;
    cudaGetSymbolAddress((void**)&S, g_scratch);
    float* G    = S;
    float* mask = S + 1ull * U2;
    float* Bv   = S + 2ull * U2;
    float* R    = S + 3ull * U2;
    float* P    = S + 4ull * U2;
    float* W    = S + 5ull * U2;     // 6 partial buffers -> through 11*U2
    __nv_bfloat16* Gh  = (__nv_bfloat16*)(S + 11ull * U2);
    __nv_bfloat16* Gl  = Gh + U2;
    __nv_bfloat16* Pbh = Gl + U2;
    __nv_bfloat16* Pbl = Pbh + U2;   // bf16 block = 2*U2 floats -> ends at 13*U2
    float* dg  = S + 13ull * U2;
    float* rho = dg + 1024;
    float* sp  = rho + 1024;

    static int smset = 0;
    if (!smset) {
        cudaFuncSetAttribute(gemm_bf16, cudaFuncAttributeMaxDynamicSharedMemorySize, 65536);
        smset = 1;
    }

    k_prep<<<1, 512>>>(ea, eb, sp);
    k_mask<<<dim3(KD / 16, KD / 16), dim3(16, 16)>>>(ea, eb, sp, mask);
    gemm_tn<<<dim3(8, 8, 3), 256>>>(A, Bm, G, Bv);
    k_transB<<<dim3(16, 16), dim3(32, 8)>>>(Bv);
    k_diag<<<4, 256>>>(G, dg);
    k_convG<<<U2 / 1024, 256>>>(G, Gh, Gl);
    k_cg_init<<<1024, 128>>>(Bv, X, R, P, mask, dg, rho, Pbh, Pbl);

    for (int i = 0; i < ITERS_BF16; i++) {
        gemm_bf16<<<dim3(4, 8, 6), 256, 65536>>>(Pbh, Pbl, Gh, Gl, W);
        k_cg_step<<<1024, 128>>>(X, R, P, W, mask, dg, rho, Pbh, Pbl, 6);
    }
    for (int i = 0; i < ITERS_F32; i++) {
        gemm_nn_sk<<<dim3(4, 8, 4), 256>>>(P, G, G + KK, W);
        k_cg_step<<<1024, 128>>>(X, R, P, W, mask, dg, rho, Pbh, Pbl, 4);
    }
}

// round 15
// speedup vs baseline: 5.4164x; 1.3476x over previous
#include <cuda_runtime.h>
#include <cuda_bf16.h>
#include <cstdint>

#define KD 512
#define DD 1024
#define KK (KD*KD)
#define U2 (2*KK)
#define LMB 1000.0f
#define ITERS_BF16 18
#define ITERS_F32  2

__device__ __align__(128) float g_scratch[13ull*U2 + 4096];

// ---------------------------------------------------------------------------
__device__ __forceinline__ uint32_t smem_u32(const void* p) {
    uint32_t a;
    asm("{ .reg .u64 t; cvta.to.shared.u64 t, %1; cvt.u32.u64 %0, t; }" : "=r"(a) : "l"(p));
    return a;
}
#define LDSM4(r0, r1, r2, r3, addr)                                         \
    asm volatile("ldmatrix.sync.aligned.m8n8.x4.shared.b16 {%0,%1,%2,%3}, [%4];" \
                 : "=r"(r0), "=r"(r1), "=r"(r2), "=r"(r3) : "r"(addr))

__device__ __forceinline__ void mma16816(float* c, uint32_t a0, uint32_t a1,
                                         uint32_t a2, uint32_t a3,
                                         uint32_t b0, uint32_t b1) {
    asm volatile("mma.sync.aligned.m16n8k16.row.col.f32.bf16.bf16.f32 "
                 "{%0,%1,%2,%3},{%4,%5,%6,%7},{%8,%9},{%0,%1,%2,%3};"
                 : "+f"(c[0]), "+f"(c[1]), "+f"(c[2]), "+f"(c[3])
                 : "r"(a0), "r"(a1), "r"(a2), "r"(a3), "r"(b0), "r"(b1));
}

#define SWZ(bo) ((bo) ^ (((bo) >> 3) & 0x70))

// ---------------------------------------------------------------------------
__global__ void k_prep(const float* __restrict__ ea, const float* __restrict__ eb,
                       float* __restrict__ sp) {
    __shared__ float sm[512];
    int t = threadIdx.x;
    sm[t] = fmaxf(ea[t], eb[t]);
    __syncthreads();
    for (int s = 256; s; s >>= 1) {
        if (t < s) sm[t] = fmaxf(sm[t], sm[t + s]);
        __syncthreads();
    }
    if (t == 0) sp[0] = sm[0];
}

__global__ void k_mask(const float* __restrict__ ea, const float* __restrict__ eb,
                       const float* __restrict__ sp, float* __restrict__ maskS) {
    int j = blockIdx.x * 16 + threadIdx.x;
    int i = blockIdx.y * 16 + threadIdx.y;
    float s = sp[0];
    float ga = ea[j] / s, gb = eb[i] / s;
    float ga2 = ga * ga + 1.f, gb2 = gb * gb + 1.f;
    float mre = gb / gb2 - ga / ga2;
    float mim = 1.f / gb2 - 1.f / ga2;
    float m = mre * mre + mim * mim;
    maskS[i * KD + j] = m;
    maskS[KK + j * KD + i] = m;
}

// Gram GEMMs (TN, fp32): z=0: G_a=A^T A ; z=1: G_b=B^T B ; z=2: Bvec_top = B^T A
__global__ __launch_bounds__(256, 2)
void gemm_tn(const float* __restrict__ A, const float* __restrict__ Bm,
             float* __restrict__ G, float* __restrict__ Bv) {
    int z = blockIdx.z;
    const float* M1 = (z == 0) ? A : Bm;
    const float* M2 = (z == 1) ? Bm : A;
    float* O = (z == 0) ? G : ((z == 1) ? (G + KK) : Bv);

    __shared__ float As[16][64];
    __shared__ float Bs[16][64];
    int row0 = blockIdx.y * 64, col0 = blockIdx.x * 64;
    int t = threadIdx.x, tx = t & 15, ty = t >> 4;
    float acc[4][4] = {};

    for (int k0 = 0; k0 < DD; k0 += 16) {
#pragma unroll
        for (int i = 0; i < 4; i++) {
            int idx = t + i * 256;
            int m = idx & 63, kk = idx >> 6;
            As[kk][m] = M1[(k0 + kk) * KD + row0 + m];
            Bs[kk][m] = M2[(k0 + kk) * KD + col0 + m];
        }
        __syncthreads();
#pragma unroll
        for (int kk = 0; kk < 16; kk++) {
            float4 a = *(const float4*)&As[kk][ty * 4];
            float4 b = *(const float4*)&Bs[kk][tx * 4];
            acc[0][0] += a.x * b.x; acc[0][1] += a.x * b.y; acc[0][2] += a.x * b.z; acc[0][3] += a.x * b.w;
            acc[1][0] += a.y * b.x; acc[1][1] += a.y * b.y; acc[1][2] += a.y * b.z; acc[1][3] += a.y * b.w;
            acc[2][0] += a.z * b.x; acc[2][1] += a.z * b.y; acc[2][2] += a.z * b.z; acc[2][3] += a.z * b.w;
            acc[3][0] += a.w * b.x; acc[3][1] += a.w * b.y; acc[3][2] += a.w * b.z; acc[3][3] += a.w * b.w;
        }
        __syncthreads();
    }
    int r = row0 + ty * 4, c = col0 + tx * 4;
#pragma unroll
    for (int i = 0; i < 4; i++) {
        float4 o = make_float4(acc[i][0], acc[i][1], acc[i][2], acc[i][3]);
        *(float4*)&O[(r + i) * KD + c] = o;
    }
}

__global__ void k_transB(float* __restrict__ Bv) {
    __shared__ float tile[32][33];
    int bx = blockIdx.x * 32, by = blockIdx.y * 32;
    int tx = threadIdx.x, ty = threadIdx.y;
#pragma unroll
    for (int i = 0; i < 32; i += 8)
        tile[ty + i][tx] = Bv[(by + ty + i) * KD + bx + tx];
    __syncthreads();
#pragma unroll
    for (int i = 0; i < 32; i += 8)
        Bv[(KD + bx + ty + i) * KD + by + tx] = tile[tx][ty + i];
}

__global__ void k_diag(const float* __restrict__ G, float* __restrict__ dg) {
    int idx = blockIdx.x * 256 + threadIdx.x;
    int d = idx >> 9, j = idx & (KD - 1);
    dg[idx] = G[d * KK + j * KD + j];
}

// G fp32 -> split bf16 (hi + lo)
__global__ void k_convG(const float* __restrict__ G, __nv_bfloat16* __restrict__ Gh,
                        __nv_bfloat16* __restrict__ Gl) {
    int i4 = (blockIdx.x * 256 + threadIdx.x) * 4;
    float4 g = *(const float4*)&G[i4];
    __nv_bfloat162 h0, h1, l0, l1;
    h0.x = __float2bfloat16(g.x); h0.y = __float2bfloat16(g.y);
    h1.x = __float2bfloat16(g.z); h1.y = __float2bfloat16(g.w);
    l0.x = __float2bfloat16(g.x - __bfloat162float(h0.x));
    l0.y = __float2bfloat16(g.y - __bfloat162float(h0.y));
    l1.x = __float2bfloat16(g.z - __bfloat162float(h1.x));
    l1.y = __float2bfloat16(g.w - __bfloat162float(h1.y));
    ((__nv_bfloat162*)(Gh + i4))[0] = h0;
    ((__nv_bfloat162*)(Gh + i4))[1] = h1;
    ((__nv_bfloat162*)(Gl + i4))[0] = l0;
    ((__nv_bfloat162*)(Gl + i4))[1] = l1;
}

// ---------------------------------------------------------------------------
// Fused 3-product bf16 matvec: W = Phi@Ghi + Phi@Glo + Plo@Ghi  (G symmetric)
// One accumulator set; split-K=2 (z). CTA tile 128(m) x 64(n), BK=64.
// Warp tile 64x16 (2m x 4n warps). 96KB dynamic smem, 2 CTAs/SM.
#define ST_PLO   16384
#define ST_GHI   32768
#define ST_GLO   40960
#define ST_STRD  49152
#define FNSTG    4

__global__ __launch_bounds__(256, 2)
void gemm_fused(const __nv_bfloat16* __restrict__ Ph, const __nv_bfloat16* __restrict__ Pl,
                const __nv_bfloat16* __restrict__ Gh, const __nv_bfloat16* __restrict__ Gl,
                float* __restrict__ Wp) {
    extern __shared__ __align__(128) char smem[];
    int z = blockIdx.z;
    int kc = z * 256;
    int r0 = blockIdx.y * 128, c0 = blockIdx.x * 64;
    size_t goff = (r0 >= KD) ? (size_t)KK : 0;
    const __nv_bfloat16* GhD = Gh + goff;
    const __nv_bfloat16* GlD = Gl + goff;
    float* Out = Wp + (size_t)z * U2;

    int t = threadIdx.x;
    int lane = t & 31, w = t >> 5;
    int wm = w >> 2, wn = w & 3;          // 2m x 4n -> warp tile 64x16
    int lrow = t >> 3, lch = t & 7;       // loaders: 32 rows/pass, 8x16B chunks
    int lrA = lane & 15, lcA = (lane >> 4) * 16;

    uint32_t sb = smem_u32(smem);
    float acc[4][2][4] = {};
    float4 vph[4], vpl[4], vgh[2], vgl[2];

    // prologue: stage 0
#pragma unroll
    for (int i = 0; i < 4; i++) {
        int row = lrow + i * 32;
        vph[i] = *(const float4*)(Ph + (size_t)(r0 + row) * KD + kc + lch * 8);
        vpl[i] = *(const float4*)(Pl + (size_t)(r0 + row) * KD + kc + lch * 8);
    }
#pragma unroll
    for (int i = 0; i < 2; i++) {
        int row = lrow + i * 32;
        vgh[i] = *(const float4*)(GhD + (size_t)(c0 + row) * KD + kc + lch * 8);
        vgl[i] = *(const float4*)(GlD + (size_t)(c0 + row) * KD + kc + lch * 8);
    }
#pragma unroll
    for (int i = 0; i < 4; i++) {
        uint32_t bo = SWZ((uint32_t)((lrow + i * 32) * 128 + lch * 16));
        *(float4*)(smem + bo) = vph[i];
        *(float4*)(smem + ST_PLO + bo) = vpl[i];
    }
#pragma unroll
    for (int i = 0; i < 2; i++) {
        uint32_t bo = SWZ((uint32_t)((lrow + i * 32) * 128 + lch * 16));
        *(float4*)(smem + ST_GHI + bo) = vgh[i];
        *(float4*)(smem + ST_GLO + bo) = vgl[i];
    }
    __syncthreads();

#pragma unroll 1
    for (int s = 0; s < FNSTG; s++) {
        uint32_t base = sb + (s & 1) * ST_STRD;
        if (s + 1 < FNSTG) {
            int k0 = kc + (s + 1) * 64;
#pragma unroll
            for (int i = 0; i < 4; i++) {
                int row = lrow + i * 32;
                vph[i] = *(const float4*)(Ph + (size_t)(r0 + row) * KD + k0 + lch * 8);
                vpl[i] = *(const float4*)(Pl + (size_t)(r0 + row) * KD + k0 + lch * 8);
            }
#pragma unroll
            for (int i = 0; i < 2; i++) {
                int row = lrow + i * 32;
                vgh[i] = *(const float4*)(GhD + (size_t)(c0 + row) * KD + k0 + lch * 8);
                vgl[i] = *(const float4*)(GlD + (size_t)(c0 + row) * KD + k0 + lch * 8);
            }
        }
#pragma unroll
        for (int kk = 0; kk < 4; kk++) {
            int rowB = wn * 16 + lrA;
            uint32_t boB = SWZ((uint32_t)(rowB * 128 + kk * 32 + lcA));
            uint32_t bh0, bh1, bh2, bh3, bl0, bl1, bl2, bl3;
            LDSM4(bh0, bh1, bh2, bh3, base + ST_GHI + boB);
            LDSM4(bl0, bl1, bl2, bl3, base + ST_GLO + boB);
#pragma unroll
            for (int tm = 0; tm < 4; tm++) {
                int rowA = wm * 64 + tm * 16 + lrA;
                uint32_t boA = SWZ((uint32_t)(rowA * 128 + kk * 32 + lcA));
                uint32_t ah0, ah1, ah2, ah3, al0, al1, al2, al3;
                LDSM4(ah0, ah1, ah2, ah3, base + boA);
                LDSM4(al0, al1, al2, al3, base + ST_PLO + boA);
                mma16816(acc[tm][0], ah0, ah1, ah2, ah3, bh0, bh2);
                mma16816(acc[tm][1], ah0, ah1, ah2, ah3, bh1, bh3);
                mma16816(acc[tm][0], ah0, ah1, ah2, ah3, bl0, bl2);
                mma16816(acc[tm][1], ah0, ah1, ah2, ah3, bl1, bl3);
                mma16816(acc[tm][0], al0, al1, al2, al3, bh0, bh2);
                mma16816(acc[tm][1], al0, al1, al2, al3, bh1, bh3);
            }
        }
        __syncthreads();
        if (s + 1 < FNSTG) {
            char* nb = smem + ((s + 1) & 1) * ST_STRD;
#pragma unroll
            for (int i = 0; i < 4; i++) {
                uint32_t bo = SWZ((uint32_t)((lrow + i * 32) * 128 + lch * 16));
                *(float4*)(nb + bo) = vph[i];
                *(float4*)(nb + ST_PLO + bo) = vpl[i];
            }
#pragma unroll
            for (int i = 0; i < 2; i++) {
                uint32_t bo = SWZ((uint32_t)((lrow + i * 32) * 128 + lch * 16));
                *(float4*)(nb + ST_GHI + bo) = vgh[i];
                *(float4*)(nb + ST_GLO + bo) = vgl[i];
            }
            __syncthreads();
        }
    }

    // epilogue: m16n8 acc layout: rows q, q+8; cols 2*(lane&3)
    int q = lane >> 2, cc = (lane & 3) * 2;
#pragma unroll
    for (int tm = 0; tm < 4; tm++)
#pragma unroll
        for (int tn = 0; tn < 2; tn++) {
            float* dst = Out + (size_t)(r0 + wm * 64 + tm * 16 + q) * KD
                             + (c0 + wn * 16 + tn * 8 + cc);
            *(float2*)dst = make_float2(acc[tm][tn][0], acc[tm][tn][1]);
            *(float2*)(dst + 8 * KD) = make_float2(acc[tm][tn][2], acc[tm][tn][3]);
        }
}

// ---------------------------------------------------------------------------
// fp32 split-K GEMM (polish iterations): Wp[z] partial over K-chunk z (4 chunks)
__global__ __launch_bounds__(256, 1)
void gemm_nn_sk(const float* __restrict__ L, const float* __restrict__ Ga,
                const float* __restrict__ Gb, float* __restrict__ Wp) {
    __shared__ float Ls[2][8][128];
    __shared__ float Rs[2][8][128];
    int r0 = blockIdx.y * 128, c0 = blockIdx.x * 128;
    int kbase = blockIdx.z * 128;
    const float* Rm = (r0 < KD) ? Ga : Gb;
    float* Out = Wp + (size_t)blockIdx.z * U2;

    int t = threadIdx.x;
    int tx = t & 15, ty = t >> 4;
    int lm = t >> 1, lk4 = (t & 1) * 4;
    int rk = t >> 5, rc4 = (t & 31) * 4;

    float acc[8][8] = {};

    float4 lv = *(const float4*)&L[(size_t)(r0 + lm) * KD + kbase + lk4];
    float4 rv = *(const float4*)&Rm[(size_t)(kbase + rk) * KD + c0 + rc4];
    Ls[0][lk4 + 0][lm] = lv.x; Ls[0][lk4 + 1][lm] = lv.y;
    Ls[0][lk4 + 2][lm] = lv.z; Ls[0][lk4 + 3][lm] = lv.w;
    *(float4*)&Rs[0][rk][rc4] = rv;
    __syncthreads();

    int buf = 0;
#pragma unroll 1
    for (int ks = 0; ks < 16; ks++) {
        if (ks + 1 < 16) {
            int k0 = kbase + (ks + 1) * 8;
            lv = *(const float4*)&L[(size_t)(r0 + lm) * KD + k0 + lk4];
            rv = *(const float4*)&Rm[(size_t)(k0 + rk) * KD + c0 + rc4];
        }
#pragma unroll
        for (int kk = 0; kk < 8; kk++) {
            float a[8], b[8];
            *(float4*)&a[0] = *(const float4*)&Ls[buf][kk][ty * 8];
            *(float4*)&a[4] = *(const float4*)&Ls[buf][kk][ty * 8 + 4];
            *(float4*)&b[0] = *(const float4*)&Rs[buf][kk][tx * 8];
            *(float4*)&b[4] = *(const float4*)&Rs[buf][kk][tx * 8 + 4];
#pragma unroll
            for (int i = 0; i < 8; i++)
#pragma unroll
                for (int j = 0; j < 8; j++) acc[i][j] += a[i] * b[j];
        }
        if (ks + 1 < 16) {
            int nb = buf ^ 1;
            Ls[nb][lk4 + 0][lm] = lv.x; Ls[nb][lk4 + 1][lm] = lv.y;
            Ls[nb][lk4 + 2][lm] = lv.z; Ls[nb][lk4 + 3][lm] = lv.w;
            *(float4*)&Rs[nb][rk][rc4] = rv;
            __syncthreads();
            buf = nb;
        }
    }

#pragma unroll
    for (int i = 0; i < 8; i++) {
        size_t off = (size_t)(r0 + ty * 8 + i) * KD + c0 + tx * 8;
        *(float4*)&Out[off]     = make_float4(acc[i][0], acc[i][1], acc[i][2], acc[i][3]);
        *(float4*)&Out[off + 4] = make_float4(acc[i][4], acc[i][5], acc[i][6], acc[i][7]);
    }
}

// ---------------------------------------------------------------------------
__device__ __forceinline__ float rowReduce(float v, float* sm, int t) {
#pragma unroll
    for (int o = 16; o; o >>= 1) v += __shfl_xor_sync(0xffffffffu, v, o);
    if ((t & 31) == 0) sm[t >> 5] = v;
    __syncthreads();
    return sm[0] + sm[1] + sm[2] + sm[3];
}

__device__ __forceinline__ void splitStore(__nv_bfloat16* Ph, __nv_bfloat16* Pl,
                                           int off, float4 p) {
    __nv_bfloat162 h0, h1, l0, l1;
    h0.x = __float2bfloat16(p.x); h0.y = __float2bfloat16(p.y);
    h1.x = __float2bfloat16(p.z); h1.y = __float2bfloat16(p.w);
    l0.x = __float2bfloat16(p.x - __bfloat162float(h0.x));
    l0.y = __float2bfloat16(p.y - __bfloat162float(h0.y));
    l1.x = __float2bfloat16(p.z - __bfloat162float(h1.x));
    l1.y = __float2bfloat16(p.w - __bfloat162float(h1.y));
    ((__nv_bfloat162*)(Ph + off))[0] = h0;
    ((__nv_bfloat162*)(Ph + off))[1] = h1;
    ((__nv_bfloat162*)(Pl + off))[0] = l0;
    ((__nv_bfloat162*)(Pl + off))[1] = l1;
}

// x=0, r=b, z=r/d, p=z (+ bf16 split of p), rho=r.z
__global__ void k_cg_init(const float* __restrict__ Bv, float* __restrict__ X,
                          float* __restrict__ R, float* __restrict__ P,
                          const float* __restrict__ mask, const float* __restrict__ dg,
                          float* __restrict__ rho,
                          __nv_bfloat16* __restrict__ Ph, __nv_bfloat16* __restrict__ Pl) {
    __shared__ float s1[4];
    int r = blockIdx.x, t = threadIdx.x;
    int off = r * KD + t * 4;
    float4 b = *(const float4*)&Bv[off];
    float4 m = *(const float4*)&mask[off];
    float4 dv = *(const float4*)&dg[((r >> 9) << 9) + t * 4];
    float4 z;
    z.x = b.x / (dv.x + LMB * m.x);
    z.y = b.y / (dv.y + LMB * m.y);
    z.z = b.z / (dv.z + LMB * m.z);
    z.w = b.w / (dv.w + LMB * m.w);
    float rz = b.x * z.x + b.y * z.y + b.z * z.z + b.w * z.w;
    rz = rowReduce(rz, s1, t);
    *(float4*)&X[off] = make_float4(0.f, 0.f, 0.f, 0.f);
    *(float4*)&R[off] = b;
    *(float4*)&P[off] = z;
    splitStore(Ph, Pl, off, z);
    if (t == 0) rho[r] = rz;
}

// w = sum_{z<np} Wp[z] + lmbda*m.*p; standard PCG step; p split to bf16
__global__ void k_cg_step(float* __restrict__ X, float* __restrict__ R,
                          float* __restrict__ P, const float* __restrict__ Wp,
                          const float* __restrict__ mask, const float* __restrict__ dg,
                          float* __restrict__ rho,
                          __nv_bfloat16* __restrict__ Ph, __nv_bfloat16* __restrict__ Pl,
                          int np) {
    __shared__ float s1[4], s2[4];
    int r = blockIdx.x, t = threadIdx.x;
    int off = r * KD + t * 4;
    float4 p  = *(const float4*)&P[off];
    float4 m  = *(const float4*)&mask[off];
    float4 dv = *(const float4*)&dg[((r >> 9) << 9) + t * 4];
    float4 w = make_float4(LMB * m.x * p.x, LMB * m.y * p.y,
                           LMB * m.z * p.z, LMB * m.w * p.w);
    for (int z = 0; z < np; z++) {
        float4 wz = *(const float4*)&Wp[(size_t)z * U2 + off];
        w.x += wz.x; w.y += wz.y; w.z += wz.z; w.w += wz.w;
    }

    float pq = p.x * w.x + p.y * w.y + p.z * w.z + p.w * w.w;
    pq = rowReduce(pq, s1, t);
    float rho_old = rho[r];
    float al = rho_old / (pq + 1e-30f);

    float4 x = *(float4*)&X[off];
    float4 rv = *(float4*)&R[off];
    x.x += al * p.x; x.y += al * p.y; x.z += al * p.z; x.w += al * p.w;
    rv.x -= al * w.x; rv.y -= al * w.y; rv.z -= al * w.z; rv.w -= al * w.w;

    float4 z4;
    z4.x = rv.x / (dv.x + LMB * m.x);
    z4.y = rv.y / (dv.y + LMB * m.y);
    z4.z = rv.z / (dv.z + LMB * m.z);
    z4.w = rv.w / (dv.w + LMB * m.w);
    float rz = rv.x * z4.x + rv.y * z4.y + rv.z * z4.z + rv.w * z4.w;
    __syncthreads();
    rz = rowReduce(rz, s2, t);
    float be = rz / (rho_old > 0.f ? rho_old + 1e-30f : (rho_old - 1e-30f));

    p.x = z4.x + be * p.x; p.y = z4.y + be * p.y;
    p.z = z4.z + be * p.z; p.w = z4.w + be * p.w;

    *(float4*)&X[off] = x;
    *(float4*)&R[off] = rv;
    *(float4*)&P[off] = p;
    splitStore(Ph, Pl, off, p);
    if (t == 0) rho[r] = rz;
}

// ---------------------------------------------------------------------------
extern "C" void kernel_launch(void* const* d_in, const int* in_sizes, int n_in,
                              void* d_out, int out_size) {
    (void)in_sizes; (void)n_in; (void)out_size;
    const float* A  = (const float*)d_in[0];
    const float* Bm = (const float*)d_in[1];
    const float* ea = (const float*)d_in[2];
    const float* eb = (const float*)d_in[3];
    float* X = (float*)d_out;

    float* S = nullptr;
    cudaGetSymbolAddress((void**)&S, g_scratch);
    float* G    = S;
    float* mask = S + 1ull * U2;
    float* Bv   = S + 2ull * U2;
    float* R    = S + 3ull * U2;
    float* P    = S + 4ull * U2;
    float* W    = S + 5ull * U2;     // 4 partial buffers -> through 9*U2
    __nv_bfloat16* Gh  = (__nv_bfloat16*)(S + 11ull * U2);
    __nv_bfloat16* Gl  = Gh + U2;
    __nv_bfloat16* Pbh = Gl + U2;
    __nv_bfloat16* Pbl = Pbh + U2;   // ends at 13*U2
    float* dg  = S + 13ull * U2;
    float* rho = dg + 1024;
    float* sp  = rho + 1024;

    static int smset = 0;
    if (!smset) {
        cudaFuncSetAttribute(gemm_fused, cudaFuncAttributeMaxDynamicSharedMemorySize, 2 * ST_STRD);
        smset = 1;
    }

    k_prep<<<1, 512>>>(ea, eb, sp);
    k_mask<<<dim3(KD / 16, KD / 16), dim3(16, 16)>>>(ea, eb, sp, mask);
    gemm_tn<<<dim3(8, 8, 3), 256>>>(A, Bm, G, Bv);
    k_transB<<<dim3(16, 16), dim3(32, 8)>>>(Bv);
    k_diag<<<4, 256>>>(G, dg);
    k_convG<<<U2 / 1024, 256>>>(G, Gh, Gl);
    k_cg_init<<<1024, 128>>>(Bv, X, R, P, mask, dg, rho, Pbh, Pbl);

    for (int i = 0; i < ITERS_BF16; i++) {
        gemm_fused<<<dim3(8, 8, 2), 256, 2 * ST_STRD>>>(Pbh, Pbl, Gh, Gl, W);
        k_cg_step<<<1024, 128>>>(X, R, P, W, mask, dg, rho, Pbh, Pbl, 2);
    }
    for (int i = 0; i < ITERS_F32; i++) {
        gemm_nn_sk<<<dim3(4, 8, 4), 256>>>(P, G, G + KK, W);
        k_cg_step<<<1024, 128>>>(X, R, P, W, mask, dg, rho, Pbh, Pbl, 4);
    }
}

// round 16
// speedup vs baseline: 5.4535x; 1.0069x over previous
#include <cuda_runtime.h>
#include <cuda_bf16.h>
#include <cstdint>

#define KD 512
#define DD 1024
#define KK (KD*KD)
#define U2 (2*KK)
#define LMB 1000.0f
#define ITERS_BF16 16
#define ITERS_F32  2

__device__ __align__(128) float g_scratch[13ull*U2 + 4096];

// ---------------------------------------------------------------------------
__device__ __forceinline__ uint32_t smem_u32(const void* p) {
    uint32_t a;
    asm("{ .reg .u64 t; cvta.to.shared.u64 t, %1; cvt.u32.u64 %0, t; }" : "=r"(a) : "l"(p));
    return a;
}
#define LDSM4(r0, r1, r2, r3, addr)                                         \
    asm volatile("ldmatrix.sync.aligned.m8n8.x4.shared.b16 {%0,%1,%2,%3}, [%4];" \
                 : "=r"(r0), "=r"(r1), "=r"(r2), "=r"(r3) : "r"(addr))

__device__ __forceinline__ void mma16816(float* c, uint32_t a0, uint32_t a1,
                                         uint32_t a2, uint32_t a3,
                                         uint32_t b0, uint32_t b1) {
    asm volatile("mma.sync.aligned.m16n8k16.row.col.f32.bf16.bf16.f32 "
                 "{%0,%1,%2,%3},{%4,%5,%6,%7},{%8,%9},{%0,%1,%2,%3};"
                 : "+f"(c[0]), "+f"(c[1]), "+f"(c[2]), "+f"(c[3])
                 : "r"(a0), "r"(a1), "r"(a2), "r"(a3), "r"(b0), "r"(b1));
}

#define SWZ(bo) ((bo) ^ (((bo) >> 3) & 0x70))

#define CPA16(smaddr, gptr)                                                 \
    asm volatile("cp.async.cg.shared.global [%0], [%1], 16;"                \
                 :: "r"(smaddr), "l"(gptr))
#define CPA_COMMIT() asm volatile("cp.async.commit_group;" ::: "memory")
#define CPA_WAIT(n)  asm volatile("cp.async.wait_group %0;" :: "n"(n) : "memory")

// ---------------------------------------------------------------------------
__global__ void k_prep(const float* __restrict__ ea, const float* __restrict__ eb,
                       float* __restrict__ sp) {
    __shared__ float sm[512];
    int t = threadIdx.x;
    sm[t] = fmaxf(ea[t], eb[t]);
    __syncthreads();
    for (int s = 256; s; s >>= 1) {
        if (t < s) sm[t] = fmaxf(sm[t], sm[t + s]);
        __syncthreads();
    }
    if (t == 0) sp[0] = sm[0];
}

__global__ void k_mask(const float* __restrict__ ea, const float* __restrict__ eb,
                       const float* __restrict__ sp, float* __restrict__ maskS) {
    int j = blockIdx.x * 16 + threadIdx.x;
    int i = blockIdx.y * 16 + threadIdx.y;
    float s = sp[0];
    float ga = ea[j] / s, gb = eb[i] / s;
    float ga2 = ga * ga + 1.f, gb2 = gb * gb + 1.f;
    float mre = gb / gb2 - ga / ga2;
    float mim = 1.f / gb2 - 1.f / ga2;
    float m = mre * mre + mim * mim;
    maskS[i * KD + j] = m;
    maskS[KK + j * KD + i] = m;
}

// Gram GEMMs (TN, fp32): z=0: G_a=A^T A ; z=1: G_b=B^T B ;
//                        z=2: Bv_top = B^T A ; z=3: Bv_bot = A^T B
__global__ __launch_bounds__(256, 2)
void gemm_tn(const float* __restrict__ A, const float* __restrict__ Bm,
             float* __restrict__ G, float* __restrict__ Bv) {
    int z = blockIdx.z;
    const float* M1 = (z == 0 || z == 3) ? A : Bm;
    const float* M2 = (z == 1 || z == 3) ? Bm : A;
    float* O = (z == 0) ? G : ((z == 1) ? (G + KK) : ((z == 2) ? Bv : (Bv + KK)));

    __shared__ float As[16][64];
    __shared__ float Bs[16][64];
    int row0 = blockIdx.y * 64, col0 = blockIdx.x * 64;
    int t = threadIdx.x, tx = t & 15, ty = t >> 4;
    float acc[4][4] = {};

    for (int k0 = 0; k0 < DD; k0 += 16) {
#pragma unroll
        for (int i = 0; i < 4; i++) {
            int idx = t + i * 256;
            int m = idx & 63, kk = idx >> 6;
            As[kk][m] = M1[(k0 + kk) * KD + row0 + m];
            Bs[kk][m] = M2[(k0 + kk) * KD + col0 + m];
        }
        __syncthreads();
#pragma unroll
        for (int kk = 0; kk < 16; kk++) {
            float4 a = *(const float4*)&As[kk][ty * 4];
            float4 b = *(const float4*)&Bs[kk][tx * 4];
            acc[0][0] += a.x * b.x; acc[0][1] += a.x * b.y; acc[0][2] += a.x * b.z; acc[0][3] += a.x * b.w;
            acc[1][0] += a.y * b.x; acc[1][1] += a.y * b.y; acc[1][2] += a.y * b.z; acc[1][3] += a.y * b.w;
            acc[2][0] += a.z * b.x; acc[2][1] += a.z * b.y; acc[2][2] += a.z * b.z; acc[2][3] += a.z * b.w;
            acc[3][0] += a.w * b.x; acc[3][1] += a.w * b.y; acc[3][2] += a.w * b.z; acc[3][3] += a.w * b.w;
        }
        __syncthreads();
    }
    int r = row0 + ty * 4, c = col0 + tx * 4;
#pragma unroll
    for (int i = 0; i < 4; i++) {
        float4 o = make_float4(acc[i][0], acc[i][1], acc[i][2], acc[i][3]);
        *(float4*)&O[(r + i) * KD + c] = o;
    }
}

// G fp32 -> split bf16 (hi + lo), with fused diagonal extraction
__global__ void k_convG(const float* __restrict__ G, __nv_bfloat16* __restrict__ Gh,
                        __nv_bfloat16* __restrict__ Gl, float* __restrict__ dg) {
    int i4 = (blockIdx.x * 256 + threadIdx.x) * 4;
    float4 g = *(const float4*)&G[i4];
    __nv_bfloat162 h0, h1, l0, l1;
    h0.x = __float2bfloat16(g.x); h0.y = __float2bfloat16(g.y);
    h1.x = __float2bfloat16(g.z); h1.y = __float2bfloat16(g.w);
    l0.x = __float2bfloat16(g.x - __bfloat162float(h0.x));
    l0.y = __float2bfloat16(g.y - __bfloat162float(h0.y));
    l1.x = __float2bfloat16(g.z - __bfloat162float(h1.x));
    l1.y = __float2bfloat16(g.w - __bfloat162float(h1.y));
    ((__nv_bfloat162*)(Gh + i4))[0] = h0;
    ((__nv_bfloat162*)(Gh + i4))[1] = h1;
    ((__nv_bfloat162*)(Gl + i4))[0] = l0;
    ((__nv_bfloat162*)(Gl + i4))[1] = l1;
    int rem = i4 & (KK - 1);
    int row = rem >> 9, col = rem & (KD - 1);
    if (row >= col && row < col + 4) {
        float v = (&g.x)[row - col];
        dg[((i4 >> 18) << 9) + row] = v;
    }
}

// ---------------------------------------------------------------------------
// Fused 3-product bf16 matvec: W = Phi@Ghi + Phi@Glo + Plo@Ghi  (G symmetric)
// One accumulator set; split-K=2 (z). CTA tile 128(m) x 64(n), BK=64.
// Warp tile 64x16 (2m x 4n warps). cp.async double-buffer, 96KB smem, 2 CTA/SM.
#define ST_PLO   16384
#define ST_GHI   32768
#define ST_GLO   40960
#define ST_STRD  49152
#define FNSTG    4

__global__ __launch_bounds__(256, 2)
void gemm_fused(const __nv_bfloat16* __restrict__ Ph, const __nv_bfloat16* __restrict__ Pl,
                const __nv_bfloat16* __restrict__ Gh, const __nv_bfloat16* __restrict__ Gl,
                float* __restrict__ Wp) {
    extern __shared__ __align__(128) char smem[];
    int z = blockIdx.z;
    int kc = z * 256;
    int r0 = blockIdx.y * 128, c0 = blockIdx.x * 64;
    size_t goff = (r0 >= KD) ? (size_t)KK : 0;
    const __nv_bfloat16* GhD = Gh + goff;
    const __nv_bfloat16* GlD = Gl + goff;
    float* Out = Wp + (size_t)z * U2;

    int t = threadIdx.x;
    int lane = t & 31, w = t >> 5;
    int wm = w >> 2, wn = w & 3;          // 2m x 4n -> warp tile 64x16
    int lrow = t >> 3, lch = t & 7;       // loaders: 32 rows/pass, 8x16B chunks
    int lrA = lane & 15, lcA = (lane >> 4) * 16;

    uint32_t sb = smem_u32(smem);
    float acc[4][2][4] = {};

    // async copy issue for stage s into buffer b
    auto issue = [&](int s, int b) {
        int k0 = kc + s * 64;
        uint32_t bufb = sb + b * ST_STRD;
#pragma unroll
        for (int i = 0; i < 4; i++) {
            int row = lrow + i * 32;
            uint32_t bo = SWZ((uint32_t)(row * 128 + lch * 16));
            CPA16(bufb + bo, Ph + (size_t)(r0 + row) * KD + k0 + lch * 8);
            CPA16(bufb + ST_PLO + bo, Pl + (size_t)(r0 + row) * KD + k0 + lch * 8);
        }
#pragma unroll
        for (int i = 0; i < 2; i++) {
            int row = lrow + i * 32;
            uint32_t bo = SWZ((uint32_t)(row * 128 + lch * 16));
            CPA16(bufb + ST_GHI + bo, GhD + (size_t)(c0 + row) * KD + k0 + lch * 8);
            CPA16(bufb + ST_GLO + bo, GlD + (size_t)(c0 + row) * KD + k0 + lch * 8);
        }
        CPA_COMMIT();
    };

    issue(0, 0);
#pragma unroll 1
    for (int s = 0; s < FNSTG; s++) {
        if (s + 1 < FNSTG) { issue(s + 1, (s + 1) & 1); CPA_WAIT(1); }
        else               { CPA_WAIT(0); }
        __syncthreads();
        uint32_t base = sb + (s & 1) * ST_STRD;
#pragma unroll
        for (int kk = 0; kk < 4; kk++) {
            int rowB = wn * 16 + lrA;
            uint32_t boB = SWZ((uint32_t)(rowB * 128 + kk * 32 + lcA));
            uint32_t bh0, bh1, bh2, bh3, bl0, bl1, bl2, bl3;
            LDSM4(bh0, bh1, bh2, bh3, base + ST_GHI + boB);
            LDSM4(bl0, bl1, bl2, bl3, base + ST_GLO + boB);
#pragma unroll
            for (int tm = 0; tm < 4; tm++) {
                int rowA = wm * 64 + tm * 16 + lrA;
                uint32_t boA = SWZ((uint32_t)(rowA * 128 + kk * 32 + lcA));
                uint32_t ah0, ah1, ah2, ah3, al0, al1, al2, al3;
                LDSM4(ah0, ah1, ah2, ah3, base + boA);
                LDSM4(al0, al1, al2, al3, base + ST_PLO + boA);
                mma16816(acc[tm][0], ah0, ah1, ah2, ah3, bh0, bh2);
                mma16816(acc[tm][1], ah0, ah1, ah2, ah3, bh1, bh3);
                mma16816(acc[tm][0], ah0, ah1, ah2, ah3, bl0, bl2);
                mma16816(acc[tm][1], ah0, ah1, ah2, ah3, bl1, bl3);
                mma16816(acc[tm][0], al0, al1, al2, al3, bh0, bh2);
                mma16816(acc[tm][1], al0, al1, al2, al3, bh1, bh3);
            }
        }
        __syncthreads();
    }

    // epilogue: m16n8 acc layout: rows q, q+8; cols 2*(lane&3)
    int q = lane >> 2, cc = (lane & 3) * 2;
#pragma unroll
    for (int tm = 0; tm < 4; tm++)
#pragma unroll
        for (int tn = 0; tn < 2; tn++) {
            float* dst = Out + (size_t)(r0 + wm * 64 + tm * 16 + q) * KD
                             + (c0 + wn * 16 + tn * 8 + cc);
            *(float2*)dst = make_float2(acc[tm][tn][0], acc[tm][tn][1]);
            *(float2*)(dst + 8 * KD) = make_float2(acc[tm][tn][2], acc[tm][tn][3]);
        }
}

// ---------------------------------------------------------------------------
// fp32 split-K GEMM (polish iterations): Wp[z] partial over K-chunk z (4 chunks)
__global__ __launch_bounds__(256, 1)
void gemm_nn_sk(const float* __restrict__ L, const float* __restrict__ Ga,
                const float* __restrict__ Gb, float* __restrict__ Wp) {
    __shared__ float Ls[2][8][128];
    __shared__ float Rs[2][8][128];
    int r0 = blockIdx.y * 128, c0 = blockIdx.x * 128;
    int kbase = blockIdx.z * 128;
    const float* Rm = (r0 < KD) ? Ga : Gb;
    float* Out = Wp + (size_t)blockIdx.z * U2;

    int t = threadIdx.x;
    int tx = t & 15, ty = t >> 4;
    int lm = t >> 1, lk4 = (t & 1) * 4;
    int rk = t >> 5, rc4 = (t & 31) * 4;

    float acc[8][8] = {};

    float4 lv = *(const float4*)&L[(size_t)(r0 + lm) * KD + kbase + lk4];
    float4 rv = *(const float4*)&Rm[(size_t)(kbase + rk) * KD + c0 + rc4];
    Ls[0][lk4 + 0][lm] = lv.x; Ls[0][lk4 + 1][lm] = lv.y;
    Ls[0][lk4 + 2][lm] = lv.z; Ls[0][lk4 + 3][lm] = lv.w;
    *(float4*)&Rs[0][rk][rc4] = rv;
    __syncthreads();

    int buf = 0;
#pragma unroll 1
    for (int ks = 0; ks < 16; ks++) {
        if (ks + 1 < 16) {
            int k0 = kbase + (ks + 1) * 8;
            lv = *(const float4*)&L[(size_t)(r0 + lm) * KD + k0 + lk4];
            rv = *(const float4*)&Rm[(size_t)(k0 + rk) * KD + c0 + rc4];
        }
#pragma unroll
        for (int kk = 0; kk < 8; kk++) {
            float a[8], b[8];
            *(float4*)&a[0] = *(const float4*)&Ls[buf][kk][ty * 8];
            *(float4*)&a[4] = *(const float4*)&Ls[buf][kk][ty * 8 + 4];
            *(float4*)&b[0] = *(const float4*)&Rs[buf][kk][tx * 8];
            *(float4*)&b[4] = *(const float4*)&Rs[buf][kk][tx * 8 + 4];
#pragma unroll
            for (int i = 0; i < 8; i++)
#pragma unroll
                for (int j = 0; j < 8; j++) acc[i][j] += a[i] * b[j];
        }
        if (ks + 1 < 16) {
            int nb = buf ^ 1;
            Ls[nb][lk4 + 0][lm] = lv.x; Ls[nb][lk4 + 1][lm] = lv.y;
            Ls[nb][lk4 + 2][lm] = lv.z; Ls[nb][lk4 + 3][lm] = lv.w;
            *(float4*)&Rs[nb][rk][rc4] = rv;
            __syncthreads();
            buf = nb;
        }
    }

#pragma unroll
    for (int i = 0; i < 8; i++) {
        size_t off = (size_t)(r0 + ty * 8 + i) * KD + c0 + tx * 8;
        *(float4*)&Out[off]     = make_float4(acc[i][0], acc[i][1], acc[i][2], acc[i][3]);
        *(float4*)&Out[off + 4] = make_float4(acc[i][4], acc[i][5], acc[i][6], acc[i][7]);
    }
}

// ---------------------------------------------------------------------------
__device__ __forceinline__ float warpSum(float v) {
#pragma unroll
    for (int o = 16; o; o >>= 1) v += __shfl_xor_sync(0xffffffffu, v, o);
    return v;
}

__device__ __forceinline__ void splitStore(__nv_bfloat16* Ph, __nv_bfloat16* Pl,
                                           int off, float4 p) {
    __nv_bfloat162 h0, h1, l0, l1;
    h0.x = __float2bfloat16(p.x); h0.y = __float2bfloat16(p.y);
    h1.x = __float2bfloat16(p.z); h1.y = __float2bfloat16(p.w);
    l0.x = __float2bfloat16(p.x - __bfloat162float(h0.x));
    l0.y = __float2bfloat16(p.y - __bfloat162float(h0.y));
    l1.x = __float2bfloat16(p.z - __bfloat162float(h1.x));
    l1.y = __float2bfloat16(p.w - __bfloat162float(h1.y));
    ((__nv_bfloat162*)(Ph + off))[0] = h0;
    ((__nv_bfloat162*)(Ph + off))[1] = h1;
    ((__nv_bfloat162*)(Pl + off))[0] = l0;
    ((__nv_bfloat162*)(Pl + off))[1] = l1;
}

// x=0, r=b, z=r/d, p=z (+ bf16 split of p), rho=r.z — warp per row
__global__ void k_cg_init(const float* __restrict__ Bv, float* __restrict__ X,
                          float* __restrict__ R, float* __restrict__ P,
                          const float* __restrict__ mask, const float* __restrict__ dg,
                          float* __restrict__ rho,
                          __nv_bfloat16* __restrict__ Ph, __nv_bfloat16* __restrict__ Pl) {
    int w = threadIdx.x >> 5, lane = threadIdx.x & 31;
    int r = blockIdx.x * 4 + w;
    int dbase = (r >> 9) << 9;
    float rz = 0.f;
#pragma unroll
    for (int j = 0; j < 4; j++) {
        int off = r * KD + lane * 4 + j * 128;
        float4 b = *(const float4*)&Bv[off];
        float4 m = *(const float4*)&mask[off];
        float4 dv = *(const float4*)&dg[dbase + lane * 4 + j * 128];
        float4 z;
        z.x = b.x / (dv.x + LMB * m.x);
        z.y = b.y / (dv.y + LMB * m.y);
        z.z = b.z / (dv.z + LMB * m.z);
        z.w = b.w / (dv.w + LMB * m.w);
        rz += b.x * z.x + b.y * z.y + b.z * z.z + b.w * z.w;
        *(float4*)&X[off] = make_float4(0.f, 0.f, 0.f, 0.f);
        *(float4*)&R[off] = b;
        *(float4*)&P[off] = z;
        splitStore(Ph, Pl, off, z);
    }
    rz = warpSum(rz);
    if (lane == 0) rho[r] = rz;
}

// Full PCG step, warp-per-row (no smem, no block sync).
__global__ void k_cg_step(float* __restrict__ X, float* __restrict__ R,
                          float* __restrict__ P, const float* __restrict__ Wp,
                          const float* __restrict__ mask, const float* __restrict__ dg,
                          float* __restrict__ rho,
                          __nv_bfloat16* __restrict__ Ph, __nv_bfloat16* __restrict__ Pl,
                          int np) {
    int w = threadIdx.x >> 5, lane = threadIdx.x & 31;
    int r = blockIdx.x * 4 + w;
    int dbase = (r >> 9) << 9;

    float4 p[4], m[4], wv[4];
    float pq = 0.f;
#pragma unroll
    for (int j = 0; j < 4; j++) {
        int off = r * KD + lane * 4 + j * 128;
        p[j] = *(const float4*)&P[off];
        m[j] = *(const float4*)&mask[off];
        float4 acc = make_float4(LMB * m[j].x * p[j].x, LMB * m[j].y * p[j].y,
                                 LMB * m[j].z * p[j].z, LMB * m[j].w * p[j].w);
        for (int z = 0; z < np; z++) {
            float4 wz = *(const float4*)&Wp[(size_t)z * U2 + off];
            acc.x += wz.x; acc.y += wz.y; acc.z += wz.z; acc.w += wz.w;
        }
        wv[j] = acc;
        pq += p[j].x * acc.x + p[j].y * acc.y + p[j].z * acc.z + p[j].w * acc.w;
    }
    pq = warpSum(pq);
    float rho_old = rho[r];
    float al = rho_old / (pq + 1e-30f);

    float4 rv[4];
    float rz = 0.f;
#pragma unroll
    for (int j = 0; j < 4; j++) {
        int off = r * KD + lane * 4 + j * 128;
        float4 x = *(float4*)&X[off];
        x.x += al * p[j].x; x.y += al * p[j].y; x.z += al * p[j].z; x.w += al * p[j].w;
        *(float4*)&X[off] = x;
        float4 rr = *(float4*)&R[off];
        rr.x -= al * wv[j].x; rr.y -= al * wv[j].y;
        rr.z -= al * wv[j].z; rr.w -= al * wv[j].w;
        rv[j] = rr;
        *(float4*)&R[off] = rr;
        float4 dv = *(const float4*)&dg[dbase + lane * 4 + j * 128];
        float4 z4;
        z4.x = rr.x / (dv.x + LMB * m[j].x);
        z4.y = rr.y / (dv.y + LMB * m[j].y);
        z4.z = rr.z / (dv.z + LMB * m[j].z);
        z4.w = rr.w / (dv.w + LMB * m[j].w);
        wv[j] = z4;  // reuse as z storage
        rz += rr.x * z4.x + rr.y * z4.y + rr.z * z4.z + rr.w * z4.w;
    }
    rz = warpSum(rz);
    float be = rz / (rho_old > 0.f ? rho_old + 1e-30f : (rho_old - 1e-30f));

#pragma unroll
    for (int j = 0; j < 4; j++) {
        int off = r * KD + lane * 4 + j * 128;
        float4 pn;
        pn.x = wv[j].x + be * p[j].x; pn.y = wv[j].y + be * p[j].y;
        pn.z = wv[j].z + be * p[j].z; pn.w = wv[j].w + be * p[j].w;
        *(float4*)&P[off] = pn;
        splitStore(Ph, Pl, off, pn);
    }
    if (lane == 0) rho[r] = rz;
}

// ---------------------------------------------------------------------------
extern "C" void kernel_launch(void* const* d_in, const int* in_sizes, int n_in,
                              void* d_out, int out_size) {
    (void)in_sizes; (void)n_in; (void)out_size;
    const float* A  = (const float*)d_in[0];
    const float* Bm = (const float*)d_in[1];
    const float* ea = (const float*)d_in[2];
    const float* eb = (const float*)d_in[3];
    float* X = (float*)d_out;

    float* S = nullptr;
    cudaGetSymbolAddress((void**)&S, g_scratch);
    float* G    = S;
    float* mask = S + 1ull * U2;
    float* Bv   = S + 2ull * U2;
    float* R    = S + 3ull * U2;
    float* P    = S + 4ull * U2;
    float* W    = S + 5ull * U2;     // 4 partial buffers -> through 9*U2
    __nv_bfloat16* Gh  = (__nv_bfloat16*)(S + 11ull * U2);
    __nv_bfloat16* Gl  = Gh + U2;
    __nv_bfloat16* Pbh = Gl + U2;
    __nv_bfloat16* Pbl = Pbh + U2;   // ends at 13*U2
    float* dg  = S + 13ull * U2;
    float* rho = dg + 1024;
    float* sp  = rho + 1024;

    static int smset = 0;
    if (!smset) {
        cudaFuncSetAttribute(gemm_fused, cudaFuncAttributeMaxDynamicSharedMemorySize, 2 * ST_STRD);
        smset = 1;
    }

    k_prep<<<1, 512>>>(ea, eb, sp);
    k_mask<<<dim3(KD / 16, KD / 16), dim3(16, 16)>>>(ea, eb, sp, mask);
    gemm_tn<<<dim3(8, 8, 4), 256>>>(A, Bm, G, Bv);
    k_convG<<<U2 / 1024, 256>>>(G, Gh, Gl, dg);
    k_cg_init<<<256, 128>>>(Bv, X, R, P, mask, dg, rho, Pbh, Pbl);

    for (int i = 0; i < ITERS_BF16; i++) {
        gemm_fused<<<dim3(8, 8, 2), 256, 2 * ST_STRD>>>(Pbh, Pbl, Gh, Gl, W);
        k_cg_step<<<256, 128>>>(X, R, P, W, mask, dg, rho, Pbh, Pbl, 2);
    }
    for (int i = 0; i < ITERS_F32; i++) {
        gemm_nn_sk<<<dim3(4, 8, 4), 256>>>(P, G, G + KK, W);
        k_cg_step<<<256, 128>>>(X, R, P, W, mask, dg, rho, Pbh, Pbl, 4);
    }
}